// round 10
// baseline (speedup 1.0000x reference)
#include <cuda_runtime.h>
#include <stdint.h>

#define BB 8
#define NN 8192
#define CC 64
#define NPOINT 2048
#define NSAMPLE 32
#define RADIUS2 0.04f
#define P_TOTAL (BB*NPOINT*NSAMPLE)   // 524288

// ---------------- scratch (device globals; no allocation allowed) ------------
__device__ float d_featT[BB*NN*CC];                 // 16.8 MB  (B,N,C)
__device__ int   d_ball_idx[P_TOTAL];
__device__ float d_h1[(size_t)64*P_TOTAL];          // 134 MB
__device__ float d_h2[(size_t)64*P_TOTAL];          // 134 MB
__device__ float d_hmx[(size_t)128*BB*NPOINT];      // 8 MB
__device__ float d_hmn[(size_t)128*BB*NPOINT];      // 8 MB
__device__ float d_partials[4096*128*2];            // 4 MB
__device__ float d_ab[128*2];                       // fused BN scale/shift
// Morton-sorted copies of xyz (+ original index)
__device__ float d_sx[BB*NN], d_sy[BB*NN], d_sz[BB*NN];
__device__ int   d_sidx[BB*NN];

// ---------------- packed f32x2 helpers (exact per-element RN) ----------------
#define PACK2(out, lo, hi)  asm("mov.b64 %0, {%1, %2};" : "=l"(out) : "f"(lo), "f"(hi))
#define UNPACK2(lo, hi, in) asm("mov.b64 {%0, %1}, %2;" : "=f"(lo), "=f"(hi) : "l"(in))
#define ADD2(out, a, b)     asm("add.rn.f32x2 %0, %1, %2;" : "=l"(out) : "l"(a), "l"(b))
#define MUL2(out, a, b)     asm("mul.rn.f32x2 %0, %1, %2;" : "=l"(out) : "l"(a), "l"(b))
#define FMA2(d, a, b, c)    asm("fma.rn.f32x2 %0, %1, %2, %3;" : "=l"(d) : "l"(a), "l"(b), "l"(c))

// ---------------- feature transpose (B,C,N) -> (B,N,C) -----------------------
__global__ void k_transpose(const float* __restrict__ f) {
    __shared__ float tile[32][33];
    int b = blockIdx.z, n0 = blockIdx.x*32, c0 = blockIdx.y*32;
    int tx = threadIdx.x, ty = threadIdx.y;
    for (int i = ty; i < 32; i += 8)
        tile[i][tx] = f[((size_t)b*CC + c0 + i)*NN + n0 + tx];
    __syncthreads();
    for (int i = ty; i < 32; i += 8)
        d_featT[((size_t)b*NN + n0 + i)*CC + c0 + tx] = tile[tx][i];
}

// ---------------- Morton counting sort: one CTA per batch --------------------
__global__ __launch_bounds__(1024,1) void k_sort(const float* __restrict__ xyz) {
    __shared__ int cnt[4096];
    __shared__ unsigned short cell[8192];
    __shared__ int wsum[32];
    int b = blockIdx.x, t = threadIdx.x;
    for (int i = t; i < 4096; i += 1024) cnt[i] = 0;
    __syncthreads();
    const float* xb = xyz + (size_t)b*NN*3;
    for (int i = t; i < NN; i += 1024) {
        float x = xb[i*3+0], y = xb[i*3+1], z = xb[i*3+2];
        int cx = min(15, max(0, (int)(x*16.0f)));
        int cy = min(15, max(0, (int)(y*16.0f)));
        int cz = min(15, max(0, (int)(z*16.0f)));
        int m = 0;
#pragma unroll
        for (int j = 0; j < 4; j++)
            m |= (((cx>>j)&1)<<(3*j)) | (((cy>>j)&1)<<(3*j+1)) | (((cz>>j)&1)<<(3*j+2));
        cell[i] = (unsigned short)m;
        atomicAdd(&cnt[m], 1);
    }
    __syncthreads();
    int c0 = cnt[t*4+0], c1 = cnt[t*4+1], c2 = cnt[t*4+2], c3 = cnt[t*4+3];
    int ts = c0+c1+c2+c3;
    int lane = t & 31, w = t >> 5;
    int x = ts;
#pragma unroll
    for (int o = 1; o < 32; o <<= 1) {
        int y = __shfl_up_sync(0xffffffffu, x, o);
        if (lane >= o) x += y;
    }
    if (lane == 31) wsum[w] = x;
    int wex = x - ts;
    __syncthreads();
    if (w == 0) {
        int v = wsum[lane];
        int xx = v;
#pragma unroll
        for (int o = 1; o < 32; o <<= 1) {
            int y = __shfl_up_sync(0xffffffffu, xx, o);
            if (lane >= o) xx += y;
        }
        wsum[lane] = xx - v;
    }
    __syncthreads();
    int basep = wsum[w] + wex;
    cnt[t*4+0] = basep;
    cnt[t*4+1] = basep + c0;
    cnt[t*4+2] = basep + c0 + c1;
    cnt[t*4+3] = basep + c0 + c1 + c2;
    __syncthreads();
    for (int i = t; i < NN; i += 1024) {
        int m = cell[i];
        int pos = atomicAdd(&cnt[m], 1);
        d_sx[b*NN+pos] = xb[i*3+0];
        d_sy[b*NN+pos] = xb[i*3+1];
        d_sz[b*NN+pos] = xb[i*3+2];
        d_sidx[b*NN+pos] = i;
    }
}

// ---------------- FPS: 1 CTA/batch, 1024 thr, 32 warps x (2 x 128 pts) -------
// Each warp owns 256 Morton-contiguous points in TWO independent 128-pt halves
// (own bounding box + cached (wmax,key) each). Skipping a half is a provable
// bitwise no-op. Tie-break keys live in smem (s_oi) to stay under 64 regs.
__global__ __launch_bounds__(1024,1) void k_fps(const float* __restrict__ xyz,
                                                float* __restrict__ out_newxyz) {
    extern __shared__ float smem[];
    float* s_px = smem;
    float* s_py = smem + 8192;
    float* s_pz = smem + 16384;
    int*   s_oi = (int*)(smem + 24576);          // 8192 ints
    __shared__ unsigned s_val[2][32];
    __shared__ unsigned s_key[2][32];

    const int b = blockIdx.x, tid = threadIdx.x;
    const int w = tid >> 5, lane = tid & 31;
    const int baseA = w*256 + lane*4;            // half A: [w*256, w*256+128)
    const int baseB = baseA + 128;               // half B: [w*256+128, w*256+256)

    float XA[4], YA[4], ZA[4], XB[4], YB[4], ZB[4];
    float ddA[4], ddB[4];
    {
        const float* sx = d_sx + b*NN;
        const float* sy = d_sy + b*NN;
        const float* sz = d_sz + b*NN;
        const int*   si = d_sidx + b*NN;
        float4 v;
        v = *(const float4*)(sx + baseA); XA[0]=v.x; XA[1]=v.y; XA[2]=v.z; XA[3]=v.w;
        v = *(const float4*)(sy + baseA); YA[0]=v.x; YA[1]=v.y; YA[2]=v.z; YA[3]=v.w;
        v = *(const float4*)(sz + baseA); ZA[0]=v.x; ZA[1]=v.y; ZA[2]=v.z; ZA[3]=v.w;
        v = *(const float4*)(sx + baseB); XB[0]=v.x; XB[1]=v.y; XB[2]=v.z; XB[3]=v.w;
        v = *(const float4*)(sy + baseB); YB[0]=v.x; YB[1]=v.y; YB[2]=v.z; YB[3]=v.w;
        v = *(const float4*)(sz + baseB); ZB[0]=v.x; ZB[1]=v.y; ZB[2]=v.z; ZB[3]=v.w;
        int4 iA = *(const int4*)(si + baseA);
        int4 iB = *(const int4*)(si + baseB);
        *(int4*)(s_oi + baseA) = iA;
        *(int4*)(s_oi + baseB) = iB;
#pragma unroll
        for (int i = 0; i < 4; i++) {
            s_px[baseA+i]=XA[i]; s_py[baseA+i]=YA[i]; s_pz[baseA+i]=ZA[i];
            s_px[baseB+i]=XB[i]; s_py[baseB+i]=YB[i]; s_pz[baseB+i]=ZB[i];
            ddA[i]=1e10f; ddB[i]=1e10f;
        }
    }
    // per-half bounding boxes (warp reduce; lanes of a warp cover each half)
    float axn=XA[0],axx=XA[0],ayn=YA[0],ayx=YA[0],azn=ZA[0],azx=ZA[0];
    float bxn=XB[0],bxx=XB[0],byn=YB[0],byx=YB[0],bzn=ZB[0],bzx=ZB[0];
#pragma unroll
    for (int i = 1; i < 4; i++) {
        axn=fminf(axn,XA[i]); axx=fmaxf(axx,XA[i]);
        ayn=fminf(ayn,YA[i]); ayx=fmaxf(ayx,YA[i]);
        azn=fminf(azn,ZA[i]); azx=fmaxf(azx,ZA[i]);
        bxn=fminf(bxn,XB[i]); bxx=fmaxf(bxx,XB[i]);
        byn=fminf(byn,YB[i]); byx=fmaxf(byx,YB[i]);
        bzn=fminf(bzn,ZB[i]); bzx=fmaxf(bzx,ZB[i]);
    }
#pragma unroll
    for (int o = 16; o >= 1; o >>= 1) {
        axn=fminf(axn,__shfl_xor_sync(0xffffffffu,axn,o));
        axx=fmaxf(axx,__shfl_xor_sync(0xffffffffu,axx,o));
        ayn=fminf(ayn,__shfl_xor_sync(0xffffffffu,ayn,o));
        ayx=fmaxf(ayx,__shfl_xor_sync(0xffffffffu,ayx,o));
        azn=fminf(azn,__shfl_xor_sync(0xffffffffu,azn,o));
        azx=fmaxf(azx,__shfl_xor_sync(0xffffffffu,azx,o));
        bxn=fminf(bxn,__shfl_xor_sync(0xffffffffu,bxn,o));
        bxx=fmaxf(bxx,__shfl_xor_sync(0xffffffffu,bxx,o));
        byn=fminf(byn,__shfl_xor_sync(0xffffffffu,byn,o));
        byx=fmaxf(byx,__shfl_xor_sync(0xffffffffu,byx,o));
        bzn=fminf(bzn,__shfl_xor_sync(0xffffffffu,bzn,o));
        bzx=fmaxf(bzx,__shfl_xor_sync(0xffffffffu,bzx,o));
    }
    // pack points into f32x2 pairs (XA.. dead afterwards)
    unsigned long long PXA[2],PYA[2],PZA[2],PXB[2],PYB[2],PZB[2];
#pragma unroll
    for (int j = 0; j < 2; j++) {
        PACK2(PXA[j],XA[2*j],XA[2*j+1]); PACK2(PYA[j],YA[2*j],YA[2*j+1]); PACK2(PZA[j],ZA[2*j],ZA[2*j+1]);
        PACK2(PXB[j],XB[2*j],XB[2*j+1]); PACK2(PYB[j],YB[2*j],YB[2*j+1]); PACK2(PZB[j],ZB[2*j],ZB[2*j+1]);
    }
    unsigned wmaxA = __float_as_uint(1e10f), wkeyA = 0xffffffffu;
    unsigned wmaxB = __float_as_uint(1e10f), wkeyB = 0xffffffffu;

    float lx, ly, lz;
    {
        const float* xb = xyz + (size_t)b*NN*3;
        lx = xb[0]; ly = xb[1]; lz = xb[2];
    }
    if (tid == 0) {
        float* o = out_newxyz + (size_t)b*NPOINT*3;
        o[0] = lx; o[1] = ly; o[2] = lz;
    }

    for (int it = 1; it < NPOINT; it++) {
        const int par = it & 1;
        // box lower bounds (conservative; 1e-4 margin absorbs rounding)
        float dxl = fmaxf(fmaxf(__fadd_rn(axn,-lx), __fadd_rn(lx,-axx)), 0.0f);
        float dyl = fmaxf(fmaxf(__fadd_rn(ayn,-ly), __fadd_rn(ly,-ayx)), 0.0f);
        float dzl = fmaxf(fmaxf(__fadd_rn(azn,-lz), __fadd_rn(lz,-azx)), 0.0f);
        float dlbA = (dxl*dxl + dyl*dyl + dzl*dzl) * 0.9999f;
        dxl = fmaxf(fmaxf(__fadd_rn(bxn,-lx), __fadd_rn(lx,-bxx)), 0.0f);
        dyl = fmaxf(fmaxf(__fadd_rn(byn,-ly), __fadd_rn(ly,-byx)), 0.0f);
        dzl = fmaxf(fmaxf(__fadd_rn(bzn,-lz), __fadd_rn(lz,-bzx)), 0.0f);
        float dlbB = (dxl*dxl + dyl*dyl + dzl*dzl) * 0.9999f;
        bool actA = dlbA < __uint_as_float(wmaxA);   // warp-uniform
        bool actB = dlbB < __uint_as_float(wmaxB);   // warp-uniform

        unsigned long long NLX, NLY, NLZ;
        if (actA || actB) {
            float nlx = -lx, nly = -ly, nlz = -lz;
            PACK2(NLX,nlx,nlx); PACK2(NLY,nly,nly); PACK2(NLZ,nlz,nlz);
        }
        if (actA) {
#pragma unroll
            for (int j = 0; j < 2; j++) {
                unsigned long long dx,dy,dz,qx,qy,qz,t,s;
                ADD2(dx,PXA[j],NLX); ADD2(dy,PYA[j],NLY); ADD2(dz,PZA[j],NLZ);
                MUL2(qx,dx,dx); MUL2(qy,dy,dy); MUL2(qz,dz,dz);
                ADD2(t,qx,qy); ADD2(s,t,qz);
                float da,db; UNPACK2(da,db,s);
                ddA[2*j]   = fminf(ddA[2*j],da);
                ddA[2*j+1] = fminf(ddA[2*j+1],db);
            }
            float lv = fmaxf(fmaxf(ddA[0],ddA[1]), fmaxf(ddA[2],ddA[3]));
            wmaxA = __reduce_max_sync(0xffffffffu, __float_as_uint(lv));
            unsigned cand = 0xffffffffu;
            if (__float_as_uint(lv) == wmaxA) {
#pragma unroll
                for (int i = 0; i < 4; i++)
                    if (__float_as_uint(ddA[i]) == wmaxA) {
                        unsigned k = ((unsigned)s_oi[baseA+i] << 13) | (unsigned)(baseA+i);
                        cand = min(cand, k);
                    }
            }
            wkeyA = __reduce_min_sync(0xffffffffu, cand);
        }
        if (actB) {
#pragma unroll
            for (int j = 0; j < 2; j++) {
                unsigned long long dx,dy,dz,qx,qy,qz,t,s;
                ADD2(dx,PXB[j],NLX); ADD2(dy,PYB[j],NLY); ADD2(dz,PZB[j],NLZ);
                MUL2(qx,dx,dx); MUL2(qy,dy,dy); MUL2(qz,dz,dz);
                ADD2(t,qx,qy); ADD2(s,t,qz);
                float da,db; UNPACK2(da,db,s);
                ddB[2*j]   = fminf(ddB[2*j],da);
                ddB[2*j+1] = fminf(ddB[2*j+1],db);
            }
            float lv = fmaxf(fmaxf(ddB[0],ddB[1]), fmaxf(ddB[2],ddB[3]));
            wmaxB = __reduce_max_sync(0xffffffffu, __float_as_uint(lv));
            unsigned cand = 0xffffffffu;
            if (__float_as_uint(lv) == wmaxB) {
#pragma unroll
                for (int i = 0; i < 4; i++)
                    if (__float_as_uint(ddB[i]) == wmaxB) {
                        unsigned k = ((unsigned)s_oi[baseB+i] << 13) | (unsigned)(baseB+i);
                        cand = min(cand, k);
                    }
            }
            wkeyB = __reduce_min_sync(0xffffffffu, cand);
        }
        // combine halves (max val; tie -> min key)
        bool aWins = (wmaxA > wmaxB) || (wmaxA == wmaxB && wkeyA < wkeyB);
        unsigned bv = aWins ? wmaxA : wmaxB;
        unsigned bk = aWins ? wkeyA : wkeyB;
        if (lane == 0) { s_val[par][w] = bv; s_key[par][w] = bk; }
        __syncthreads();
        // redundant global reduce in every warp (32 slots == 32 lanes)
        unsigned v  = s_val[par][lane];
        unsigned m  = __reduce_max_sync(0xffffffffu, v);
        unsigned ck = (v == m) ? s_key[par][lane] : 0xffffffffu;
        unsigned gk = __reduce_min_sync(0xffffffffu, ck);
        int p = (int)(gk & 8191u);
        lx = s_px[p]; ly = s_py[p]; lz = s_pz[p];
        if (tid == 0) {
            float* o2 = out_newxyz + ((size_t)b*NPOINT + it)*3;
            o2[0] = lx; o2[1] = ly; o2[2] = lz;
        }
    }
}

// ---------------- ball query: smem-staged, 32 queries per 1024-thr CTA -------
__global__ __launch_bounds__(1024,2) void k_ballquery(const float* __restrict__ xyz,
                                                      const float* __restrict__ newxyz) {
    extern __shared__ float sm[];
    float* sx = sm;
    float* sy = sm + 8192;
    float* sz = sm + 16384;
    int tid = threadIdx.x;
    int b = blockIdx.x >> 6;
    int qbase = (blockIdx.x & 63) * 32;

    const float* xb = xyz + (size_t)b*NN*3;
    for (int p = tid; p < NN; p += 1024) {
        sx[p] = xb[3*p+0];
        sy[p] = xb[3*p+1];
        sz[p] = xb[3*p+2];
    }
    __syncthreads();

    int w = tid >> 5, lane = tid & 31;
    int s = qbase + w;
    int gq = b*NPOINT + s;
    const float* np = newxyz + (size_t)gq*3;
    float qx = np[0], qy = np[1], qz = np[2];
    int* outp = d_ball_idx + (size_t)gq*NSAMPLE;

    int cnt = 0, firstIdx = 0; bool haveFirst = false;
    for (int j0 = 0; j0 < NN && cnt < NSAMPLE; j0 += 32) {
        int j = j0 + lane;
        float dx = __fadd_rn(sx[j], -qx);
        float dy = __fadd_rn(sy[j], -qy);
        float dz = __fadd_rn(sz[j], -qz);
        float d = __fadd_rn(__fadd_rn(__fmul_rn(dx,dx), __fmul_rn(dy,dy)),
                            __fmul_rn(dz,dz));
        bool in = d < RADIUS2;
        unsigned mm = __ballot_sync(0xffffffffu, in);
        if (mm) {
            if (!haveFirst) { firstIdx = j0 + __ffs(mm) - 1; haveFirst = true; }
            if (in) {
                int pos = cnt + __popc(mm & ((1u << lane) - 1u));
                if (pos < NSAMPLE) outp[pos] = j;
            }
            cnt += __popc(mm);
        }
    }
    int fs = cnt < NSAMPLE ? cnt : NSAMPLE;
    for (int pos = fs + lane; pos < NSAMPLE; pos += 32) outp[pos] = firstIdx;
}

// ======== packed-FMA 8x8 micro-kernel (R6 form — best measured) ===============
#define MM8x8_K(sw_row, sg_row)                                               \
    do {                                                                      \
        float wv[8], g[8];                                                    \
        *(float4*)&wv[0] = *(const float4*)&(sw_row)[0];                      \
        *(float4*)&wv[4] = *(const float4*)&(sw_row)[4];                      \
        *(float4*)&g[0]  = *(const float4*)&(sg_row)[0];                      \
        *(float4*)&g[4]  = *(const float4*)&(sg_row)[4];                      \
        unsigned long long g2[4];                                             \
        PACK2(g2[0], g[0], g[1]); PACK2(g2[1], g[2], g[3]);                   \
        PACK2(g2[2], g[4], g[5]); PACK2(g2[3], g[6], g[7]);                   \
        _Pragma("unroll")                                                     \
        for (int i = 0; i < 8; i++) {                                         \
            unsigned long long w2; PACK2(w2, wv[i], wv[i]);                   \
            FMA2(acc2[i][0], w2, g2[0], acc2[i][0]);                          \
            FMA2(acc2[i][1], w2, g2[1], acc2[i][1]);                          \
            FMA2(acc2[i][2], w2, g2[2], acc2[i][2]);                          \
            FMA2(acc2[i][3], w2, g2[3], acc2[i][3]);                          \
        }                                                                     \
    } while (0)

// ---------------- layer 1: gather + GEMM(64x67) + stat partials --------------
__global__ __launch_bounds__(256,2) void k_layer1(const float* __restrict__ xyz,
                                                  const float* __restrict__ newxyz,
                                                  const float* __restrict__ W1) {
    extern __shared__ float sm[];
    float (*sg)[256] = (float(*)[256])sm;              // 67 x 256
    float (*sw)[64]  = (float(*)[64])(sm + 67*256);    // 67 x 64
    int tid = threadIdx.x;
    int pos0 = blockIdx.x * 256;

    for (int i = tid; i < 64*67; i += 256) { int o = i/67, c = i%67; sw[c][o] = W1[i]; }
    {
        int pos = pos0 + tid;
        int idx = d_ball_idx[pos];
        int b = pos >> 16;
        int s = (pos >> 5) & 2047;
        const float* nx = newxyz + ((size_t)b*NPOINT + s)*3;
        const float* pp = xyz + ((size_t)b*NN + idx)*3;
        sg[0][tid] = pp[0]-nx[0];
        sg[1][tid] = pp[1]-nx[1];
        sg[2][tid] = pp[2]-nx[2];
        const float4* fr = (const float4*)(d_featT + ((size_t)b*NN + idx)*CC);
#pragma unroll
        for (int c4 = 0; c4 < 16; c4++) {
            float4 v = fr[c4];
            sg[3+c4*4+0][tid] = v.x; sg[3+c4*4+1][tid] = v.y;
            sg[3+c4*4+2][tid] = v.z; sg[3+c4*4+3][tid] = v.w;
        }
    }
    __syncthreads();

    int tr = tid >> 5, tc = tid & 31;
    unsigned long long acc2[8][4];
#pragma unroll
    for (int i=0;i<8;i++)
#pragma unroll
        for (int j=0;j<4;j++) acc2[i][j]=0ull;

#pragma unroll 2
    for (int k = 0; k < 67; k++)
        MM8x8_K(&sw[k][tr*8], &sg[k][tc*8]);

    float acc[8][8];
#pragma unroll
    for (int i=0;i<8;i++)
#pragma unroll
        for (int j=0;j<4;j++) UNPACK2(acc[i][2*j], acc[i][2*j+1], acc2[i][j]);

#pragma unroll
    for (int i = 0; i < 8; i++) {
        int c = tr*8 + i;
        float* hp = d_h1 + (size_t)c*P_TOTAL + pos0 + tc*8;
        *(float4*)hp     = make_float4(acc[i][0],acc[i][1],acc[i][2],acc[i][3]);
        *(float4*)(hp+4) = make_float4(acc[i][4],acc[i][5],acc[i][6],acc[i][7]);
    }
#pragma unroll
    for (int i = 0; i < 8; i++) {
        float s = 0.f, q = 0.f;
#pragma unroll
        for (int j = 0; j < 8; j++) { s += acc[i][j]; q += acc[i][j]*acc[i][j]; }
#pragma unroll
        for (int o = 16; o > 0; o >>= 1) {
            s += __shfl_xor_sync(0xffffffffu, s, o);
            q += __shfl_xor_sync(0xffffffffu, q, o);
        }
        if (tc == 0) {
            int c = tr*8 + i;
            d_partials[((size_t)blockIdx.x*128 + c)*2 + 0] = s;
            d_partials[((size_t)blockIdx.x*128 + c)*2 + 1] = q;
        }
    }
}

// ---------------- deterministic stats reduce + BN fold -----------------------
__global__ void k_stats(const float* __restrict__ gam, const float* __restrict__ bet,
                        int nblocks) {
    int c = blockIdx.x, t = threadIdx.x;
    double s = 0.0, q = 0.0;
    for (int i = t; i < nblocks; i += 256) {
        s += (double)d_partials[((size_t)i*128 + c)*2 + 0];
        q += (double)d_partials[((size_t)i*128 + c)*2 + 1];
    }
    __shared__ double ss[256], qq[256];
    ss[t] = s; qq[t] = q; __syncthreads();
    for (int o = 128; o > 0; o >>= 1) {
        if (t < o) { ss[t] += ss[t+o]; qq[t] += qq[t+o]; }
        __syncthreads();
    }
    if (t == 0) {
        double mu  = ss[0] / (double)P_TOTAL;
        double var = qq[0] / (double)P_TOTAL - mu*mu;
        float a  = (float)((double)gam[c] / sqrt(var + 1e-5));
        float bp = (float)((double)bet[c] - mu * (double)a);
        d_ab[c*2] = a; d_ab[c*2+1] = bp;
    }
}

// ---------------- layer 2: bn1+relu on load, GEMM(64x64) ---------------------
__global__ __launch_bounds__(256,2) void k_layer2(const float* __restrict__ W2) {
    extern __shared__ float sm[];
    float (*sg)[256] = (float(*)[256])sm;              // 64 x 256
    float (*sw)[64]  = (float(*)[64])(sm + 64*256);    // 64 x 64
    int tid = threadIdx.x;
    int pos0 = blockIdx.x * 256;
    int wid = tid >> 5, lane = tid & 31;

    for (int i = tid; i < 64*64; i += 256) { int o = i/64, c = i%64; sw[c][o] = W2[i]; }
    for (int c = wid; c < 64; c += 8) {
        float a = d_ab[c*2], bp = d_ab[c*2+1];
        const float4* src = (const float4*)(d_h1 + (size_t)c*P_TOTAL + pos0) + lane*2;
        float4 v0 = src[0], v1 = src[1];
        v0.x=fmaxf(0.f,a*v0.x+bp); v0.y=fmaxf(0.f,a*v0.y+bp);
        v0.z=fmaxf(0.f,a*v0.z+bp); v0.w=fmaxf(0.f,a*v0.w+bp);
        v1.x=fmaxf(0.f,a*v1.x+bp); v1.y=fmaxf(0.f,a*v1.y+bp);
        v1.z=fmaxf(0.f,a*v1.z+bp); v1.w=fmaxf(0.f,a*v1.w+bp);
        *(float4*)&sg[c][lane*8]   = v0;
        *(float4*)&sg[c][lane*8+4] = v1;
    }
    __syncthreads();

    int tr = wid, tc = lane;
    unsigned long long acc2[8][4];
#pragma unroll
    for (int i=0;i<8;i++)
#pragma unroll
        for (int j=0;j<4;j++) acc2[i][j]=0ull;

#pragma unroll 2
    for (int k = 0; k < 64; k++)
        MM8x8_K(&sw[k][tr*8], &sg[k][tc*8]);

    float acc[8][8];
#pragma unroll
    for (int i=0;i<8;i++)
#pragma unroll
        for (int j=0;j<4;j++) UNPACK2(acc[i][2*j], acc[i][2*j+1], acc2[i][j]);

#pragma unroll
    for (int i = 0; i < 8; i++) {
        int c = tr*8 + i;
        float* hp = d_h2 + (size_t)c*P_TOTAL + pos0 + tc*8;
        *(float4*)hp     = make_float4(acc[i][0],acc[i][1],acc[i][2],acc[i][3]);
        *(float4*)(hp+4) = make_float4(acc[i][4],acc[i][5],acc[i][6],acc[i][7]);
    }
#pragma unroll
    for (int i = 0; i < 8; i++) {
        float s = 0.f, q = 0.f;
#pragma unroll
        for (int j = 0; j < 8; j++) { s += acc[i][j]; q += acc[i][j]*acc[i][j]; }
#pragma unroll
        for (int o = 16; o > 0; o >>= 1) {
            s += __shfl_xor_sync(0xffffffffu, s, o);
            q += __shfl_xor_sync(0xffffffffu, q, o);
        }
        if (tc == 0) {
            int c = tr*8 + i;
            d_partials[((size_t)blockIdx.x*128 + c)*2 + 0] = s;
            d_partials[((size_t)blockIdx.x*128 + c)*2 + 1] = q;
        }
    }
}

// ---------------- layer 3: bn2+relu on load, GEMM(128x64), fused max/min -----
__global__ __launch_bounds__(256,2) void k_layer3(const float* __restrict__ W3) {
    extern __shared__ float sm[];
    float (*sg)[128] = (float(*)[128])sm;              // 64 x 128
    float (*sw)[128] = (float(*)[128])(sm + 64*128);   // 64 x 128
    int tid = threadIdx.x;
    int pos0 = blockIdx.x * 128;
    int wid = tid >> 5, lane = tid & 31;

    for (int i = tid; i < 128*64; i += 256) { int o = i/64, c = i%64; sw[c][o] = W3[i]; }
    for (int c = wid; c < 64; c += 8) {
        float a = d_ab[c*2], bp = d_ab[c*2+1];
        const float4* src = (const float4*)(d_h2 + (size_t)c*P_TOTAL + pos0);
        float4 v = src[lane];
        v.x=fmaxf(0.f,a*v.x+bp); v.y=fmaxf(0.f,a*v.y+bp);
        v.z=fmaxf(0.f,a*v.z+bp); v.w=fmaxf(0.f,a*v.w+bp);
        *(float4*)&sg[c][lane*4] = v;
    }
    __syncthreads();

    int tr = tid >> 4, tc = tid & 15;
    unsigned long long acc2[8][4];
#pragma unroll
    for (int i=0;i<8;i++)
#pragma unroll
        for (int j=0;j<4;j++) acc2[i][j]=0ull;

#pragma unroll 2
    for (int k = 0; k < 64; k++)
        MM8x8_K(&sw[k][tr*8], &sg[k][tc*8]);

    float acc[8][8];
#pragma unroll
    for (int i=0;i<8;i++)
#pragma unroll
        for (int j=0;j<4;j++) UNPACK2(acc[i][2*j], acc[i][2*j+1], acc2[i][j]);

    int sglob = (pos0 >> 5) + (tc >> 2);
#pragma unroll
    for (int i = 0; i < 8; i++) {
        int c = tr*8 + i;
        float mx = acc[i][0], mn = acc[i][0];
#pragma unroll
        for (int j = 1; j < 8; j++) { mx = fmaxf(mx, acc[i][j]); mn = fminf(mn, acc[i][j]); }
        mx = fmaxf(mx, __shfl_xor_sync(0xffffffffu, mx, 1));
        mn = fminf(mn, __shfl_xor_sync(0xffffffffu, mn, 1));
        mx = fmaxf(mx, __shfl_xor_sync(0xffffffffu, mx, 2));
        mn = fminf(mn, __shfl_xor_sync(0xffffffffu, mn, 2));
        if ((tc & 3) == 0) {
            d_hmx[(size_t)c*(BB*NPOINT) + sglob] = mx;
            d_hmn[(size_t)c*(BB*NPOINT) + sglob] = mn;
        }
    }
#pragma unroll
    for (int i = 0; i < 8; i++) {
        float s = 0.f, q = 0.f;
#pragma unroll
        for (int j = 0; j < 8; j++) { s += acc[i][j]; q += acc[i][j]*acc[i][j]; }
#pragma unroll
        for (int o = 8; o > 0; o >>= 1) {
            s += __shfl_xor_sync(0xffffffffu, s, o);
            q += __shfl_xor_sync(0xffffffffu, q, o);
        }
        if (tc == 0) {
            int c = tr*8 + i;
            d_partials[((size_t)blockIdx.x*128 + c)*2 + 0] = s;
            d_partials[((size_t)blockIdx.x*128 + c)*2 + 1] = q;
        }
    }
}

// ---------------- bn3 + relu on the pooled extremum --------------------------
__global__ void k_finalize(float* __restrict__ feats) {
    int gid = blockIdx.x*blockDim.x + threadIdx.x;
    if (gid >= BB*128*NPOINT) return;
    int s = gid & 2047;
    int o = (gid >> 11) & 127;
    int b = gid >> 18;
    float a = d_ab[o*2], bp = d_ab[o*2+1];
    size_t ix = (size_t)o*(BB*NPOINT) + b*NPOINT + s;
    float v = (a >= 0.0f) ? d_hmx[ix] : d_hmn[ix];
    feats[gid] = fmaxf(0.0f, a*v + bp);
}

// ---------------- launch ------------------------------------------------------
extern "C" void kernel_launch(void* const* d_in, const int* in_sizes, int n_in,
                              void* d_out, int out_size) {
    const float* xyz      = (const float*)d_in[0];
    const float* features = (const float*)d_in[1];
    const float* W1 = (const float*)d_in[2];
    const float* g1 = (const float*)d_in[3];
    const float* b1 = (const float*)d_in[4];
    const float* W2 = (const float*)d_in[5];
    const float* g2 = (const float*)d_in[6];
    const float* b2 = (const float*)d_in[7];
    const float* W3 = (const float*)d_in[8];
    const float* g3 = (const float*)d_in[9];
    const float* b3 = (const float*)d_in[10];
    float* out    = (float*)d_out;
    float* newxyz = out;                       // 8*2048*3
    float* feats  = out + BB*NPOINT*3;         // 8*128*2048

    const int SMF = 4*NN*4;                    // 128KB: px,py,pz,oi
    const int SMQ = 3*NN*4;                    // 96KB ballquery stage
    const int SM1 = (67*256 + 67*64) * 4;      // 85760
    const int SM2 = (64*256 + 64*64) * 4;      // 81920
    const int SM3 = (64*128 + 64*128) * 4;     // 65536
    cudaFuncSetAttribute(k_fps,       cudaFuncAttributeMaxDynamicSharedMemorySize, SMF);
    cudaFuncSetAttribute(k_ballquery, cudaFuncAttributeMaxDynamicSharedMemorySize, SMQ);
    cudaFuncSetAttribute(k_layer1,    cudaFuncAttributeMaxDynamicSharedMemorySize, SM1);
    cudaFuncSetAttribute(k_layer2,    cudaFuncAttributeMaxDynamicSharedMemorySize, SM2);
    cudaFuncSetAttribute(k_layer3,    cudaFuncAttributeMaxDynamicSharedMemorySize, SM3);

    k_transpose<<<dim3(NN/32, CC/32, BB), dim3(32,8)>>>(features);
    k_sort<<<BB, 1024>>>(xyz);
    k_fps<<<BB, 1024, SMF>>>(xyz, newxyz);
    k_ballquery<<<BB*64, 1024, SMQ>>>(xyz, newxyz);

    k_layer1<<<P_TOTAL/256, 256, SM1>>>(xyz, newxyz, W1);
    k_stats<<<64, 256>>>(g1, b1, P_TOTAL/256);
    k_layer2<<<P_TOTAL/256, 256, SM2>>>(W2);
    k_stats<<<64, 256>>>(g2, b2, P_TOTAL/256);
    k_layer3<<<P_TOTAL/128, 256, SM3>>>(W3);
    k_stats<<<128, 256>>>(g3, b3, P_TOTAL/128);
    k_finalize<<<(BB*128*NPOINT)/256, 256>>>(feats);
}

// round 11
// speedup vs baseline: 1.3869x; 1.3869x over previous
#include <cuda_runtime.h>
#include <stdint.h>

#define BB 8
#define NN 8192
#define CC 64
#define NPOINT 2048
#define NSAMPLE 32
#define RADIUS2 0.04f
#define P_TOTAL (BB*NPOINT*NSAMPLE)   // 524288

// ---------------- scratch (device globals; no allocation allowed) ------------
__device__ float d_featT[BB*NN*CC];                 // 16.8 MB  (B,N,C)
__device__ int   d_ball_idx[P_TOTAL];
__device__ float d_h1[(size_t)64*P_TOTAL];          // 134 MB
__device__ float d_h2[(size_t)64*P_TOTAL];          // 134 MB
__device__ float d_hmx[(size_t)128*BB*NPOINT];      // 8 MB
__device__ float d_hmn[(size_t)128*BB*NPOINT];      // 8 MB
__device__ float d_partials[4096*128*2];            // 4 MB
__device__ float d_ab[128*2];                       // fused BN scale/shift
// Morton-sorted copies of xyz (+ original index)
__device__ float d_sx[BB*NN], d_sy[BB*NN], d_sz[BB*NN];
__device__ int   d_sidx[BB*NN];

// ---------------- packed f32x2 helpers (exact per-element RN) ----------------
#define PACK2(out, lo, hi)  asm("mov.b64 %0, {%1, %2};" : "=l"(out) : "f"(lo), "f"(hi))
#define UNPACK2(lo, hi, in) asm("mov.b64 {%0, %1}, %2;" : "=f"(lo), "=f"(hi) : "l"(in))
#define ADD2(out, a, b)     asm("add.rn.f32x2 %0, %1, %2;" : "=l"(out) : "l"(a), "l"(b))
#define MUL2(out, a, b)     asm("mul.rn.f32x2 %0, %1, %2;" : "=l"(out) : "l"(a), "l"(b))
#define FMA2(d, a, b, c)    asm("fma.rn.f32x2 %0, %1, %2, %3;" : "=l"(d) : "l"(a), "l"(b), "l"(c))

// ---------------- feature transpose (B,C,N) -> (B,N,C) -----------------------
__global__ void k_transpose(const float* __restrict__ f) {
    __shared__ float tile[32][33];
    int b = blockIdx.z, n0 = blockIdx.x*32, c0 = blockIdx.y*32;
    int tx = threadIdx.x, ty = threadIdx.y;
    for (int i = ty; i < 32; i += 8)
        tile[i][tx] = f[((size_t)b*CC + c0 + i)*NN + n0 + tx];
    __syncthreads();
    for (int i = ty; i < 32; i += 8)
        d_featT[((size_t)b*NN + n0 + i)*CC + c0 + tx] = tile[tx][i];
}

// ---------------- Morton counting sort: one CTA per batch --------------------
__global__ __launch_bounds__(1024,1) void k_sort(const float* __restrict__ xyz) {
    __shared__ int cnt[4096];
    __shared__ unsigned short cell[8192];
    __shared__ int wsum[32];
    int b = blockIdx.x, t = threadIdx.x;
    for (int i = t; i < 4096; i += 1024) cnt[i] = 0;
    __syncthreads();
    const float* xb = xyz + (size_t)b*NN*3;
    for (int i = t; i < NN; i += 1024) {
        float x = xb[i*3+0], y = xb[i*3+1], z = xb[i*3+2];
        int cx = min(15, max(0, (int)(x*16.0f)));
        int cy = min(15, max(0, (int)(y*16.0f)));
        int cz = min(15, max(0, (int)(z*16.0f)));
        int m = 0;
#pragma unroll
        for (int j = 0; j < 4; j++)
            m |= (((cx>>j)&1)<<(3*j)) | (((cy>>j)&1)<<(3*j+1)) | (((cz>>j)&1)<<(3*j+2));
        cell[i] = (unsigned short)m;
        atomicAdd(&cnt[m], 1);
    }
    __syncthreads();
    int c0 = cnt[t*4+0], c1 = cnt[t*4+1], c2 = cnt[t*4+2], c3 = cnt[t*4+3];
    int ts = c0+c1+c2+c3;
    int lane = t & 31, w = t >> 5;
    int x = ts;
#pragma unroll
    for (int o = 1; o < 32; o <<= 1) {
        int y = __shfl_up_sync(0xffffffffu, x, o);
        if (lane >= o) x += y;
    }
    if (lane == 31) wsum[w] = x;
    int wex = x - ts;
    __syncthreads();
    if (w == 0) {
        int v = wsum[lane];
        int xx = v;
#pragma unroll
        for (int o = 1; o < 32; o <<= 1) {
            int y = __shfl_up_sync(0xffffffffu, xx, o);
            if (lane >= o) xx += y;
        }
        wsum[lane] = xx - v;
    }
    __syncthreads();
    int basep = wsum[w] + wex;
    cnt[t*4+0] = basep;
    cnt[t*4+1] = basep + c0;
    cnt[t*4+2] = basep + c0 + c1;
    cnt[t*4+3] = basep + c0 + c1 + c2;
    __syncthreads();
    for (int i = t; i < NN; i += 1024) {
        int m = cell[i];
        int pos = atomicAdd(&cnt[m], 1);
        d_sx[b*NN+pos] = xb[i*3+0];
        d_sy[b*NN+pos] = xb[i*3+1];
        d_sz[b*NN+pos] = xb[i*3+2];
        d_sidx[b*NN+pos] = i;
    }
}

// ---------------- FPS: 1 CTA/batch, 1024 thr, 32 warps x 256 pts (R9 form) ---
__global__ __launch_bounds__(1024,1) void k_fps(const float* __restrict__ xyz,
                                                float* __restrict__ out_newxyz) {
    extern __shared__ float smem[];
    float* s_px = smem;
    float* s_py = smem + 8192;
    float* s_pz = smem + 16384;
    __shared__ unsigned s_val[2][32];
    __shared__ unsigned s_key[2][32];

    const int b = blockIdx.x, tid = threadIdx.x;
    const int w = tid >> 5, lane = tid & 31;
    const int base = w*256 + lane*8;

    float X[8], Y[8], Z[8], dd[8];
    unsigned OIK[8];
    {
        const float* sx = d_sx + b*NN;
        const float* sy = d_sy + b*NN;
        const float* sz = d_sz + b*NN;
        const int*   si = d_sidx + b*NN;
#pragma unroll
        for (int q = 0; q < 2; q++) {
            float4 vx = *(const float4*)(sx + base + q*4);
            float4 vy = *(const float4*)(sy + base + q*4);
            float4 vz = *(const float4*)(sz + base + q*4);
            int4   vi = *(const int4*)  (si + base + q*4);
            X[q*4+0]=vx.x; X[q*4+1]=vx.y; X[q*4+2]=vx.z; X[q*4+3]=vx.w;
            Y[q*4+0]=vy.x; Y[q*4+1]=vy.y; Y[q*4+2]=vy.z; Y[q*4+3]=vy.w;
            Z[q*4+0]=vz.x; Z[q*4+1]=vz.y; Z[q*4+2]=vz.z; Z[q*4+3]=vz.w;
            OIK[q*4+0]=((unsigned)vi.x<<13)|(unsigned)(base+q*4+0);
            OIK[q*4+1]=((unsigned)vi.y<<13)|(unsigned)(base+q*4+1);
            OIK[q*4+2]=((unsigned)vi.z<<13)|(unsigned)(base+q*4+2);
            OIK[q*4+3]=((unsigned)vi.w<<13)|(unsigned)(base+q*4+3);
        }
#pragma unroll
        for (int i = 0; i < 8; i++) {
            s_px[base+i]=X[i]; s_py[base+i]=Y[i]; s_pz[base+i]=Z[i];
            dd[i]=1e10f;
        }
    }
    float bxn=X[0],bxx=X[0],byn=Y[0],byx=Y[0],bzn=Z[0],bzx=Z[0];
#pragma unroll
    for (int i = 1; i < 8; i++) {
        bxn=fminf(bxn,X[i]); bxx=fmaxf(bxx,X[i]);
        byn=fminf(byn,Y[i]); byx=fmaxf(byx,Y[i]);
        bzn=fminf(bzn,Z[i]); bzx=fmaxf(bzx,Z[i]);
    }
#pragma unroll
    for (int o = 16; o >= 1; o >>= 1) {
        bxn=fminf(bxn,__shfl_xor_sync(0xffffffffu,bxn,o));
        bxx=fmaxf(bxx,__shfl_xor_sync(0xffffffffu,bxx,o));
        byn=fminf(byn,__shfl_xor_sync(0xffffffffu,byn,o));
        byx=fmaxf(byx,__shfl_xor_sync(0xffffffffu,byx,o));
        bzn=fminf(bzn,__shfl_xor_sync(0xffffffffu,bzn,o));
        bzx=fmaxf(bzx,__shfl_xor_sync(0xffffffffu,bzx,o));
    }
    unsigned long long PX[4],PY[4],PZ[4];
#pragma unroll
    for (int j = 0; j < 4; j++) {
        PACK2(PX[j],X[2*j],X[2*j+1]);
        PACK2(PY[j],Y[2*j],Y[2*j+1]);
        PACK2(PZ[j],Z[2*j],Z[2*j+1]);
    }
    unsigned wmax = __float_as_uint(1e10f), wkey = 0xffffffffu;

    float lx, ly, lz;
    {
        const float* xb = xyz + (size_t)b*NN*3;
        lx = xb[0]; ly = xb[1]; lz = xb[2];
    }
    if (tid == 0) {
        float* o = out_newxyz + (size_t)b*NPOINT*3;
        o[0] = lx; o[1] = ly; o[2] = lz;
    }

    for (int it = 1; it < NPOINT; it++) {
        const int par = it & 1;
        float dxl = fmaxf(fmaxf(__fadd_rn(bxn,-lx), __fadd_rn(lx,-bxx)), 0.0f);
        float dyl = fmaxf(fmaxf(__fadd_rn(byn,-ly), __fadd_rn(ly,-byx)), 0.0f);
        float dzl = fmaxf(fmaxf(__fadd_rn(bzn,-lz), __fadd_rn(lz,-bzx)), 0.0f);
        float dlb = (dxl*dxl + dyl*dyl + dzl*dzl) * 0.9999f;
        if (dlb < __uint_as_float(wmax)) {
            float nlx = -lx, nly = -ly, nlz = -lz;
            unsigned long long NLX, NLY, NLZ;
            PACK2(NLX,nlx,nlx); PACK2(NLY,nly,nly); PACK2(NLZ,nlz,nlz);
            float lv = 0.0f;
#pragma unroll
            for (int j = 0; j < 4; j++) {
                unsigned long long dx,dy,dz,qx,qy,qz,t,s;
                ADD2(dx,PX[j],NLX); ADD2(dy,PY[j],NLY); ADD2(dz,PZ[j],NLZ);
                MUL2(qx,dx,dx); MUL2(qy,dy,dy); MUL2(qz,dz,dz);
                ADD2(t,qx,qy); ADD2(s,t,qz);
                float da,db; UNPACK2(da,db,s);
                dd[2*j]   = fminf(dd[2*j],da);
                dd[2*j+1] = fminf(dd[2*j+1],db);
                lv = fmaxf(lv, fmaxf(dd[2*j], dd[2*j+1]));
            }
            wmax = __reduce_max_sync(0xffffffffu, __float_as_uint(lv));
            unsigned cand = 0xffffffffu;
            if (__float_as_uint(lv) == wmax) {
#pragma unroll
                for (int i = 0; i < 8; i++)
                    if (__float_as_uint(dd[i]) == wmax) cand = min(cand, OIK[i]);
            }
            wkey = __reduce_min_sync(0xffffffffu, cand);
        }
        if (lane == 0) { s_val[par][w] = wmax; s_key[par][w] = wkey; }
        __syncthreads();
        unsigned v  = s_val[par][lane];
        unsigned m  = __reduce_max_sync(0xffffffffu, v);
        unsigned ck = (v == m) ? s_key[par][lane] : 0xffffffffu;
        unsigned gk = __reduce_min_sync(0xffffffffu, ck);
        int p = (int)(gk & 8191u);
        lx = s_px[p]; ly = s_py[p]; lz = s_pz[p];
        if (tid == 0) {
            float* o2 = out_newxyz + ((size_t)b*NPOINT + it)*3;
            o2[0] = lx; o2[1] = ly; o2[2] = lz;
        }
    }
}

// ---------------- ball query: smem-staged, 32 queries per 1024-thr CTA -------
__global__ __launch_bounds__(1024,2) void k_ballquery(const float* __restrict__ xyz,
                                                      const float* __restrict__ newxyz) {
    extern __shared__ float sm[];
    float* sx = sm;
    float* sy = sm + 8192;
    float* sz = sm + 16384;
    int tid = threadIdx.x;
    int b = blockIdx.x >> 6;
    int qbase = (blockIdx.x & 63) * 32;

    const float* xb = xyz + (size_t)b*NN*3;
    for (int p = tid; p < NN; p += 1024) {
        sx[p] = xb[3*p+0];
        sy[p] = xb[3*p+1];
        sz[p] = xb[3*p+2];
    }
    __syncthreads();

    int w = tid >> 5, lane = tid & 31;
    int s = qbase + w;
    int gq = b*NPOINT + s;
    const float* np = newxyz + (size_t)gq*3;
    float qx = np[0], qy = np[1], qz = np[2];
    int* outp = d_ball_idx + (size_t)gq*NSAMPLE;

    int cnt = 0, firstIdx = 0; bool haveFirst = false;
    for (int j0 = 0; j0 < NN && cnt < NSAMPLE; j0 += 32) {
        int j = j0 + lane;
        float dx = __fadd_rn(sx[j], -qx);
        float dy = __fadd_rn(sy[j], -qy);
        float dz = __fadd_rn(sz[j], -qz);
        float d = __fadd_rn(__fadd_rn(__fmul_rn(dx,dx), __fmul_rn(dy,dy)),
                            __fmul_rn(dz,dz));
        bool in = d < RADIUS2;
        unsigned mm = __ballot_sync(0xffffffffu, in);
        if (mm) {
            if (!haveFirst) { firstIdx = j0 + __ffs(mm) - 1; haveFirst = true; }
            if (in) {
                int pos = cnt + __popc(mm & ((1u << lane) - 1u));
                if (pos < NSAMPLE) outp[pos] = j;
            }
            cnt += __popc(mm);
        }
    }
    int fs = cnt < NSAMPLE ? cnt : NSAMPLE;
    for (int pos = fs + lane; pos < NSAMPLE; pos += 32) outp[pos] = firstIdx;
}

// ======== packed-FMA 4x8 micro-kernel (512-thr layers) ========================
#define MM4x8_K(sw_row, sg_row)                                               \
    do {                                                                      \
        float wv[4], g[8];                                                    \
        *(float4*)&wv[0] = *(const float4*)&(sw_row)[0];                      \
        *(float4*)&g[0]  = *(const float4*)&(sg_row)[0];                      \
        *(float4*)&g[4]  = *(const float4*)&(sg_row)[4];                      \
        unsigned long long g2[4];                                             \
        PACK2(g2[0], g[0], g[1]); PACK2(g2[1], g[2], g[3]);                   \
        PACK2(g2[2], g[4], g[5]); PACK2(g2[3], g[6], g[7]);                   \
        _Pragma("unroll")                                                     \
        for (int i = 0; i < 4; i++) {                                         \
            unsigned long long w2; PACK2(w2, wv[i], wv[i]);                   \
            FMA2(acc2[i][0], w2, g2[0], acc2[i][0]);                          \
            FMA2(acc2[i][1], w2, g2[1], acc2[i][1]);                          \
            FMA2(acc2[i][2], w2, g2[2], acc2[i][2]);                          \
            FMA2(acc2[i][3], w2, g2[3], acc2[i][3]);                          \
        }                                                                     \
    } while (0)

// ---------------- layer 1: gather + GEMM(64x67) + stat partials --------------
// 512 thr, thread tile 4 out x 8 pos (tr=tid>>5 in 0..15, tc=tid&31).
__global__ __launch_bounds__(512,2) void k_layer1(const float* __restrict__ xyz,
                                                  const float* __restrict__ newxyz,
                                                  const float* __restrict__ W1) {
    extern __shared__ float sm[];
    float (*sg)[256] = (float(*)[256])sm;              // 67 x 256
    float (*sw)[64]  = (float(*)[64])(sm + 67*256);    // 67 x 64
    int tid = threadIdx.x;
    int pos0 = blockIdx.x * 256;

    for (int i = tid; i < 64*67; i += 512) { int o = i/67, c = i%67; sw[c][o] = W1[i]; }
    {   // two threads per position: half 0 = xyz + c4 0..7, half 1 = c4 8..15
        int pr = tid >> 1, hf = tid & 1;
        int pos = pos0 + pr;
        int idx = d_ball_idx[pos];
        int b = pos >> 16;
        int s = (pos >> 5) & 2047;
        if (hf == 0) {
            const float* nx = newxyz + ((size_t)b*NPOINT + s)*3;
            const float* pp = xyz + ((size_t)b*NN + idx)*3;
            sg[0][pr] = pp[0]-nx[0];
            sg[1][pr] = pp[1]-nx[1];
            sg[2][pr] = pp[2]-nx[2];
        }
        const float4* fr = (const float4*)(d_featT + ((size_t)b*NN + idx)*CC) + hf*8;
#pragma unroll
        for (int c4 = 0; c4 < 8; c4++) {
            float4 v = fr[c4];
            int cb = 3 + (hf*8 + c4)*4;
            sg[cb+0][pr] = v.x; sg[cb+1][pr] = v.y;
            sg[cb+2][pr] = v.z; sg[cb+3][pr] = v.w;
        }
    }
    __syncthreads();

    int tr = tid >> 5, tc = tid & 31;
    unsigned long long acc2[4][4];
#pragma unroll
    for (int i=0;i<4;i++)
#pragma unroll
        for (int j=0;j<4;j++) acc2[i][j]=0ull;

#pragma unroll 2
    for (int k = 0; k < 67; k++)
        MM4x8_K(&sw[k][tr*4], &sg[k][tc*8]);

    float acc[4][8];
#pragma unroll
    for (int i=0;i<4;i++)
#pragma unroll
        for (int j=0;j<4;j++) UNPACK2(acc[i][2*j], acc[i][2*j+1], acc2[i][j]);

#pragma unroll
    for (int i = 0; i < 4; i++) {
        int c = tr*4 + i;
        float* hp = d_h1 + (size_t)c*P_TOTAL + pos0 + tc*8;
        *(float4*)hp     = make_float4(acc[i][0],acc[i][1],acc[i][2],acc[i][3]);
        *(float4*)(hp+4) = make_float4(acc[i][4],acc[i][5],acc[i][6],acc[i][7]);
    }
#pragma unroll
    for (int i = 0; i < 4; i++) {
        float s = 0.f, q = 0.f;
#pragma unroll
        for (int j = 0; j < 8; j++) { s += acc[i][j]; q += acc[i][j]*acc[i][j]; }
#pragma unroll
        for (int o = 16; o > 0; o >>= 1) {
            s += __shfl_xor_sync(0xffffffffu, s, o);
            q += __shfl_xor_sync(0xffffffffu, q, o);
        }
        if (tc == 0) {
            int c = tr*4 + i;
            d_partials[((size_t)blockIdx.x*128 + c)*2 + 0] = s;
            d_partials[((size_t)blockIdx.x*128 + c)*2 + 1] = q;
        }
    }
}

// ---------------- deterministic stats reduce + BN fold -----------------------
__global__ void k_stats(const float* __restrict__ gam, const float* __restrict__ bet,
                        int nblocks) {
    int c = blockIdx.x, t = threadIdx.x;
    double s = 0.0, q = 0.0;
    for (int i = t; i < nblocks; i += 256) {
        s += (double)d_partials[((size_t)i*128 + c)*2 + 0];
        q += (double)d_partials[((size_t)i*128 + c)*2 + 1];
    }
    __shared__ double ss[256], qq[256];
    ss[t] = s; qq[t] = q; __syncthreads();
    for (int o = 128; o > 0; o >>= 1) {
        if (t < o) { ss[t] += ss[t+o]; qq[t] += qq[t+o]; }
        __syncthreads();
    }
    if (t == 0) {
        double mu  = ss[0] / (double)P_TOTAL;
        double var = qq[0] / (double)P_TOTAL - mu*mu;
        float a  = (float)((double)gam[c] / sqrt(var + 1e-5));
        float bp = (float)((double)bet[c] - mu * (double)a);
        d_ab[c*2] = a; d_ab[c*2+1] = bp;
    }
}

// ---------------- layer 2: bn1+relu on load, GEMM(64x64), 512 thr ------------
__global__ __launch_bounds__(512,2) void k_layer2(const float* __restrict__ W2) {
    extern __shared__ float sm[];
    float (*sg)[256] = (float(*)[256])sm;              // 64 x 256
    float (*sw)[64]  = (float(*)[64])(sm + 64*256);    // 64 x 64
    int tid = threadIdx.x;
    int pos0 = blockIdx.x * 256;
    int wid = tid >> 5, lane = tid & 31;

    for (int i = tid; i < 64*64; i += 512) { int o = i/64, c = i%64; sw[c][o] = W2[i]; }
    for (int c = wid; c < 64; c += 16) {
        float a = d_ab[c*2], bp = d_ab[c*2+1];
        const float4* src = (const float4*)(d_h1 + (size_t)c*P_TOTAL + pos0) + lane*2;
        float4 v0 = src[0], v1 = src[1];
        v0.x=fmaxf(0.f,a*v0.x+bp); v0.y=fmaxf(0.f,a*v0.y+bp);
        v0.z=fmaxf(0.f,a*v0.z+bp); v0.w=fmaxf(0.f,a*v0.w+bp);
        v1.x=fmaxf(0.f,a*v1.x+bp); v1.y=fmaxf(0.f,a*v1.y+bp);
        v1.z=fmaxf(0.f,a*v1.z+bp); v1.w=fmaxf(0.f,a*v1.w+bp);
        *(float4*)&sg[c][lane*8]   = v0;
        *(float4*)&sg[c][lane*8+4] = v1;
    }
    __syncthreads();

    int tr = tid >> 5, tc = tid & 31;
    unsigned long long acc2[4][4];
#pragma unroll
    for (int i=0;i<4;i++)
#pragma unroll
        for (int j=0;j<4;j++) acc2[i][j]=0ull;

#pragma unroll 2
    for (int k = 0; k < 64; k++)
        MM4x8_K(&sw[k][tr*4], &sg[k][tc*8]);

    float acc[4][8];
#pragma unroll
    for (int i=0;i<4;i++)
#pragma unroll
        for (int j=0;j<4;j++) UNPACK2(acc[i][2*j], acc[i][2*j+1], acc2[i][j]);

#pragma unroll
    for (int i = 0; i < 4; i++) {
        int c = tr*4 + i;
        float* hp = d_h2 + (size_t)c*P_TOTAL + pos0 + tc*8;
        *(float4*)hp     = make_float4(acc[i][0],acc[i][1],acc[i][2],acc[i][3]);
        *(float4*)(hp+4) = make_float4(acc[i][4],acc[i][5],acc[i][6],acc[i][7]);
    }
#pragma unroll
    for (int i = 0; i < 4; i++) {
        float s = 0.f, q = 0.f;
#pragma unroll
        for (int j = 0; j < 8; j++) { s += acc[i][j]; q += acc[i][j]*acc[i][j]; }
#pragma unroll
        for (int o = 16; o > 0; o >>= 1) {
            s += __shfl_xor_sync(0xffffffffu, s, o);
            q += __shfl_xor_sync(0xffffffffu, q, o);
        }
        if (tc == 0) {
            int c = tr*4 + i;
            d_partials[((size_t)blockIdx.x*128 + c)*2 + 0] = s;
            d_partials[((size_t)blockIdx.x*128 + c)*2 + 1] = q;
        }
    }
}

// ---------------- layer 3: bn2+relu on load, GEMM(128x64), fused max/min -----
// 512 thr, tile 128 out x 128 pos, thread tile 4x8 (tr=tid>>4 in 0..31, tc=tid&15)
__global__ __launch_bounds__(512,2) void k_layer3(const float* __restrict__ W3) {
    extern __shared__ float sm[];
    float (*sg)[128] = (float(*)[128])sm;              // 64 x 128
    float (*sw)[128] = (float(*)[128])(sm + 64*128);   // 64 x 128
    int tid = threadIdx.x;
    int pos0 = blockIdx.x * 128;
    int wid = tid >> 5, lane = tid & 31;

    for (int i = tid; i < 128*64; i += 512) { int o = i/64, c = i%64; sw[c][o] = W3[i]; }
    for (int c = wid; c < 64; c += 16) {
        float a = d_ab[c*2], bp = d_ab[c*2+1];
        const float4* src = (const float4*)(d_h2 + (size_t)c*P_TOTAL + pos0);
        float4 v = src[lane];
        v.x=fmaxf(0.f,a*v.x+bp); v.y=fmaxf(0.f,a*v.y+bp);
        v.z=fmaxf(0.f,a*v.z+bp); v.w=fmaxf(0.f,a*v.w+bp);
        *(float4*)&sg[c][lane*4] = v;
    }
    __syncthreads();

    int tr = tid >> 4, tc = tid & 15;
    unsigned long long acc2[4][4];
#pragma unroll
    for (int i=0;i<4;i++)
#pragma unroll
        for (int j=0;j<4;j++) acc2[i][j]=0ull;

#pragma unroll 2
    for (int k = 0; k < 64; k++)
        MM4x8_K(&sw[k][tr*4], &sg[k][tc*8]);

    float acc[4][8];
#pragma unroll
    for (int i=0;i<4;i++)
#pragma unroll
        for (int j=0;j<4;j++) UNPACK2(acc[i][2*j], acc[i][2*j+1], acc2[i][j]);

    int sglob = (pos0 >> 5) + (tc >> 2);
#pragma unroll
    for (int i = 0; i < 4; i++) {
        int c = tr*4 + i;
        float mx = acc[i][0], mn = acc[i][0];
#pragma unroll
        for (int j = 1; j < 8; j++) { mx = fmaxf(mx, acc[i][j]); mn = fminf(mn, acc[i][j]); }
        mx = fmaxf(mx, __shfl_xor_sync(0xffffffffu, mx, 1));
        mn = fminf(mn, __shfl_xor_sync(0xffffffffu, mn, 1));
        mx = fmaxf(mx, __shfl_xor_sync(0xffffffffu, mx, 2));
        mn = fminf(mn, __shfl_xor_sync(0xffffffffu, mn, 2));
        if ((tc & 3) == 0) {
            d_hmx[(size_t)c*(BB*NPOINT) + sglob] = mx;
            d_hmn[(size_t)c*(BB*NPOINT) + sglob] = mn;
        }
    }
#pragma unroll
    for (int i = 0; i < 4; i++) {
        float s = 0.f, q = 0.f;
#pragma unroll
        for (int j = 0; j < 8; j++) { s += acc[i][j]; q += acc[i][j]*acc[i][j]; }
#pragma unroll
        for (int o = 8; o > 0; o >>= 1) {   // reduce within 16-lane half (same tr)
            s += __shfl_xor_sync(0xffffffffu, s, o);
            q += __shfl_xor_sync(0xffffffffu, q, o);
        }
        if (tc == 0) {
            int c = tr*4 + i;
            d_partials[((size_t)blockIdx.x*128 + c)*2 + 0] = s;
            d_partials[((size_t)blockIdx.x*128 + c)*2 + 1] = q;
        }
    }
}

// ---------------- bn3 + relu on the pooled extremum --------------------------
__global__ void k_finalize(float* __restrict__ feats) {
    int gid = blockIdx.x*blockDim.x + threadIdx.x;
    if (gid >= BB*128*NPOINT) return;
    int s = gid & 2047;
    int o = (gid >> 11) & 127;
    int b = gid >> 18;
    float a = d_ab[o*2], bp = d_ab[o*2+1];
    size_t ix = (size_t)o*(BB*NPOINT) + b*NPOINT + s;
    float v = (a >= 0.0f) ? d_hmx[ix] : d_hmn[ix];
    feats[gid] = fmaxf(0.0f, a*v + bp);
}

// ---------------- launch ------------------------------------------------------
extern "C" void kernel_launch(void* const* d_in, const int* in_sizes, int n_in,
                              void* d_out, int out_size) {
    const float* xyz      = (const float*)d_in[0];
    const float* features = (const float*)d_in[1];
    const float* W1 = (const float*)d_in[2];
    const float* g1 = (const float*)d_in[3];
    const float* b1 = (const float*)d_in[4];
    const float* W2 = (const float*)d_in[5];
    const float* g2 = (const float*)d_in[6];
    const float* b2 = (const float*)d_in[7];
    const float* W3 = (const float*)d_in[8];
    const float* g3 = (const float*)d_in[9];
    const float* b3 = (const float*)d_in[10];
    float* out    = (float*)d_out;
    float* newxyz = out;                       // 8*2048*3
    float* feats  = out + BB*NPOINT*3;         // 8*128*2048

    const int SMF = 3*NN*4;                    // 96KB FPS point cache
    const int SMQ = 3*NN*4;                    // 96KB ballquery stage
    const int SM1 = (67*256 + 67*64) * 4;      // 85760
    const int SM2 = (64*256 + 64*64) * 4;      // 81920
    const int SM3 = (64*128 + 64*128) * 4;     // 65536
    cudaFuncSetAttribute(k_fps,       cudaFuncAttributeMaxDynamicSharedMemorySize, SMF);
    cudaFuncSetAttribute(k_ballquery, cudaFuncAttributeMaxDynamicSharedMemorySize, SMQ);
    cudaFuncSetAttribute(k_layer1,    cudaFuncAttributeMaxDynamicSharedMemorySize, SM1);
    cudaFuncSetAttribute(k_layer2,    cudaFuncAttributeMaxDynamicSharedMemorySize, SM2);
    cudaFuncSetAttribute(k_layer3,    cudaFuncAttributeMaxDynamicSharedMemorySize, SM3);

    k_transpose<<<dim3(NN/32, CC/32, BB), dim3(32,8)>>>(features);
    k_sort<<<BB, 1024>>>(xyz);
    k_fps<<<BB, 1024, SMF>>>(xyz, newxyz);
    k_ballquery<<<BB*64, 1024, SMQ>>>(xyz, newxyz);

    k_layer1<<<P_TOTAL/256, 512, SM1>>>(xyz, newxyz, W1);
    k_stats<<<64, 256>>>(g1, b1, P_TOTAL/256);
    k_layer2<<<P_TOTAL/256, 512, SM2>>>(W2);
    k_stats<<<64, 256>>>(g2, b2, P_TOTAL/256);
    k_layer3<<<P_TOTAL/128, 512, SM3>>>(W3);
    k_stats<<<128, 256>>>(g3, b3, P_TOTAL/128);
    k_finalize<<<(BB*128*NPOINT)/256, 256>>>(feats);
}

// round 12
// speedup vs baseline: 1.4383x; 1.0371x over previous
#include <cuda_runtime.h>
#include <stdint.h>

#define BB 8
#define NN 8192
#define CC 64
#define NPOINT 2048
#define NSAMPLE 32
#define RADIUS2 0.04f
#define P_TOTAL (BB*NPOINT*NSAMPLE)   // 524288

// ---------------- scratch (device globals; no allocation allowed) ------------
__device__ float d_featT[BB*NN*CC];                 // 16.8 MB  (B,N,C)
__device__ int   d_ball_idx[P_TOTAL];
__device__ float d_h1[(size_t)64*P_TOTAL];          // 134 MB
__device__ float d_h2[(size_t)64*P_TOTAL];          // 134 MB
__device__ float d_hmx[(size_t)128*BB*NPOINT];      // 8 MB
__device__ float d_hmn[(size_t)128*BB*NPOINT];      // 8 MB
__device__ float d_partials[4096*128*2];            // 4 MB
__device__ float d_ab[128*2];                       // fused BN scale/shift
// Morton-sorted copies of xyz (+ original index)
__device__ float d_sx[BB*NN], d_sy[BB*NN], d_sz[BB*NN];
__device__ int   d_sidx[BB*NN];

// ---------------- packed f32x2 helpers (exact per-element RN) ----------------
#define PACK2(out, lo, hi)  asm("mov.b64 %0, {%1, %2};" : "=l"(out) : "f"(lo), "f"(hi))
#define UNPACK2(lo, hi, in) asm("mov.b64 {%0, %1}, %2;" : "=f"(lo), "=f"(hi) : "l"(in))
#define ADD2(out, a, b)     asm("add.rn.f32x2 %0, %1, %2;" : "=l"(out) : "l"(a), "l"(b))
#define MUL2(out, a, b)     asm("mul.rn.f32x2 %0, %1, %2;" : "=l"(out) : "l"(a), "l"(b))
#define FMA2(d, a, b, c)    asm("fma.rn.f32x2 %0, %1, %2, %3;" : "=l"(d) : "l"(a), "l"(b), "l"(c))

// ---------------- feature transpose (B,C,N) -> (B,N,C) -----------------------
__global__ void k_transpose(const float* __restrict__ f) {
    __shared__ float tile[32][33];
    int b = blockIdx.z, n0 = blockIdx.x*32, c0 = blockIdx.y*32;
    int tx = threadIdx.x, ty = threadIdx.y;
    for (int i = ty; i < 32; i += 8)
        tile[i][tx] = f[((size_t)b*CC + c0 + i)*NN + n0 + tx];
    __syncthreads();
    for (int i = ty; i < 32; i += 8)
        d_featT[((size_t)b*NN + n0 + i)*CC + c0 + tx] = tile[tx][i];
}

// ---------------- Morton counting sort: one CTA per batch --------------------
__global__ __launch_bounds__(1024,1) void k_sort(const float* __restrict__ xyz) {
    __shared__ int cnt[4096];
    __shared__ unsigned short cell[8192];
    __shared__ int wsum[32];
    int b = blockIdx.x, t = threadIdx.x;
    for (int i = t; i < 4096; i += 1024) cnt[i] = 0;
    __syncthreads();
    const float* xb = xyz + (size_t)b*NN*3;
    for (int i = t; i < NN; i += 1024) {
        float x = xb[i*3+0], y = xb[i*3+1], z = xb[i*3+2];
        int cx = min(15, max(0, (int)(x*16.0f)));
        int cy = min(15, max(0, (int)(y*16.0f)));
        int cz = min(15, max(0, (int)(z*16.0f)));
        int m = 0;
#pragma unroll
        for (int j = 0; j < 4; j++)
            m |= (((cx>>j)&1)<<(3*j)) | (((cy>>j)&1)<<(3*j+1)) | (((cz>>j)&1)<<(3*j+2));
        cell[i] = (unsigned short)m;
        atomicAdd(&cnt[m], 1);
    }
    __syncthreads();
    int c0 = cnt[t*4+0], c1 = cnt[t*4+1], c2 = cnt[t*4+2], c3 = cnt[t*4+3];
    int ts = c0+c1+c2+c3;
    int lane = t & 31, w = t >> 5;
    int x = ts;
#pragma unroll
    for (int o = 1; o < 32; o <<= 1) {
        int y = __shfl_up_sync(0xffffffffu, x, o);
        if (lane >= o) x += y;
    }
    if (lane == 31) wsum[w] = x;
    int wex = x - ts;
    __syncthreads();
    if (w == 0) {
        int v = wsum[lane];
        int xx = v;
#pragma unroll
        for (int o = 1; o < 32; o <<= 1) {
            int y = __shfl_up_sync(0xffffffffu, xx, o);
            if (lane >= o) xx += y;
        }
        wsum[lane] = xx - v;
    }
    __syncthreads();
    int basep = wsum[w] + wex;
    cnt[t*4+0] = basep;
    cnt[t*4+1] = basep + c0;
    cnt[t*4+2] = basep + c0 + c1;
    cnt[t*4+3] = basep + c0 + c1 + c2;
    __syncthreads();
    for (int i = t; i < NN; i += 1024) {
        int m = cell[i];
        int pos = atomicAdd(&cnt[m], 1);
        d_sx[b*NN+pos] = xb[i*3+0];
        d_sy[b*NN+pos] = xb[i*3+1];
        d_sz[b*NN+pos] = xb[i*3+2];
        d_sidx[b*NN+pos] = i;
    }
}

// ---------------- FPS: 1 CTA/batch, 1024 thr, 32 warps x 256 pts -------------
// R9 structure; winner coords cached as float4 (1 LDS.128 on the chain) and
// newxyz output register-staged in warp0, flushed every 32 iterations.
__global__ __launch_bounds__(1024,1) void k_fps(const float* __restrict__ xyz,
                                                float* __restrict__ out_newxyz) {
    extern __shared__ float smem[];
    float4* s_pt = (float4*)smem;                // 8192 x float4 = 128KB
    __shared__ unsigned s_val[2][32];
    __shared__ unsigned s_key[2][32];

    const int b = blockIdx.x, tid = threadIdx.x;
    const int w = tid >> 5, lane = tid & 31;
    const int base = w*256 + lane*8;

    float X[8], Y[8], Z[8], dd[8];
    unsigned OIK[8];
    {
        const float* sx = d_sx + b*NN;
        const float* sy = d_sy + b*NN;
        const float* sz = d_sz + b*NN;
        const int*   si = d_sidx + b*NN;
#pragma unroll
        for (int q = 0; q < 2; q++) {
            float4 vx = *(const float4*)(sx + base + q*4);
            float4 vy = *(const float4*)(sy + base + q*4);
            float4 vz = *(const float4*)(sz + base + q*4);
            int4   vi = *(const int4*)  (si + base + q*4);
            X[q*4+0]=vx.x; X[q*4+1]=vx.y; X[q*4+2]=vx.z; X[q*4+3]=vx.w;
            Y[q*4+0]=vy.x; Y[q*4+1]=vy.y; Y[q*4+2]=vy.z; Y[q*4+3]=vy.w;
            Z[q*4+0]=vz.x; Z[q*4+1]=vz.y; Z[q*4+2]=vz.z; Z[q*4+3]=vz.w;
            OIK[q*4+0]=((unsigned)vi.x<<13)|(unsigned)(base+q*4+0);
            OIK[q*4+1]=((unsigned)vi.y<<13)|(unsigned)(base+q*4+1);
            OIK[q*4+2]=((unsigned)vi.z<<13)|(unsigned)(base+q*4+2);
            OIK[q*4+3]=((unsigned)vi.w<<13)|(unsigned)(base+q*4+3);
        }
#pragma unroll
        for (int i = 0; i < 8; i++) {
            s_pt[base+i] = make_float4(X[i], Y[i], Z[i], 0.0f);
            dd[i]=1e10f;
        }
    }
    float bxn=X[0],bxx=X[0],byn=Y[0],byx=Y[0],bzn=Z[0],bzx=Z[0];
#pragma unroll
    for (int i = 1; i < 8; i++) {
        bxn=fminf(bxn,X[i]); bxx=fmaxf(bxx,X[i]);
        byn=fminf(byn,Y[i]); byx=fmaxf(byx,Y[i]);
        bzn=fminf(bzn,Z[i]); bzx=fmaxf(bzx,Z[i]);
    }
#pragma unroll
    for (int o = 16; o >= 1; o >>= 1) {
        bxn=fminf(bxn,__shfl_xor_sync(0xffffffffu,bxn,o));
        bxx=fmaxf(bxx,__shfl_xor_sync(0xffffffffu,bxx,o));
        byn=fminf(byn,__shfl_xor_sync(0xffffffffu,byn,o));
        byx=fmaxf(byx,__shfl_xor_sync(0xffffffffu,byx,o));
        bzn=fminf(bzn,__shfl_xor_sync(0xffffffffu,bzn,o));
        bzx=fmaxf(bzx,__shfl_xor_sync(0xffffffffu,bzx,o));
    }
    unsigned long long PX[4],PY[4],PZ[4];
#pragma unroll
    for (int j = 0; j < 4; j++) {
        PACK2(PX[j],X[2*j],X[2*j+1]);
        PACK2(PY[j],Y[2*j],Y[2*j+1]);
        PACK2(PZ[j],Z[2*j],Z[2*j+1]);
    }
    unsigned wmax = __float_as_uint(1e10f), wkey = 0xffffffffu;

    float lx, ly, lz;
    {
        const float* xb = xyz + (size_t)b*NN*3;
        lx = xb[0]; ly = xb[1]; lz = xb[2];
    }
    // register-staged output (warp0): lane (i&31) holds iteration i's point
    float rx = lx, ry = ly, rz = lz;             // lane0 holds iteration 0

    for (int it = 1; it < NPOINT; it++) {
        const int par = it & 1;
        float dxl = fmaxf(fmaxf(__fadd_rn(bxn,-lx), __fadd_rn(lx,-bxx)), 0.0f);
        float dyl = fmaxf(fmaxf(__fadd_rn(byn,-ly), __fadd_rn(ly,-byx)), 0.0f);
        float dzl = fmaxf(fmaxf(__fadd_rn(bzn,-lz), __fadd_rn(lz,-bzx)), 0.0f);
        float dlb = (dxl*dxl + dyl*dyl + dzl*dzl) * 0.9999f;
        if (dlb < __uint_as_float(wmax)) {
            float nlx = -lx, nly = -ly, nlz = -lz;
            unsigned long long NLX, NLY, NLZ;
            PACK2(NLX,nlx,nlx); PACK2(NLY,nly,nly); PACK2(NLZ,nlz,nlz);
            float lv = 0.0f;
#pragma unroll
            for (int j = 0; j < 4; j++) {
                unsigned long long dx,dy,dz,qx,qy,qz,t,s;
                ADD2(dx,PX[j],NLX); ADD2(dy,PY[j],NLY); ADD2(dz,PZ[j],NLZ);
                MUL2(qx,dx,dx); MUL2(qy,dy,dy); MUL2(qz,dz,dz);
                ADD2(t,qx,qy); ADD2(s,t,qz);
                float da,db; UNPACK2(da,db,s);
                dd[2*j]   = fminf(dd[2*j],da);
                dd[2*j+1] = fminf(dd[2*j+1],db);
                lv = fmaxf(lv, fmaxf(dd[2*j], dd[2*j+1]));
            }
            wmax = __reduce_max_sync(0xffffffffu, __float_as_uint(lv));
            unsigned cand = 0xffffffffu;
            if (__float_as_uint(lv) == wmax) {
#pragma unroll
                for (int i = 0; i < 8; i++)
                    if (__float_as_uint(dd[i]) == wmax) cand = min(cand, OIK[i]);
            }
            wkey = __reduce_min_sync(0xffffffffu, cand);
        }
        if (lane == 0) { s_val[par][w] = wmax; s_key[par][w] = wkey; }
        __syncthreads();
        unsigned v  = s_val[par][lane];
        unsigned m  = __reduce_max_sync(0xffffffffu, v);
        unsigned ck = (v == m) ? s_key[par][lane] : 0xffffffffu;
        unsigned gk = __reduce_min_sync(0xffffffffu, ck);
        float4 p = s_pt[gk & 8191u];
        lx = p.x; ly = p.y; lz = p.z;
        if (w == 0) {
            if (lane == (it & 31)) { rx = lx; ry = ly; rz = lz; }
            if ((it & 31) == 31) {      // flush iterations it-31 .. it
                float* o = out_newxyz + ((size_t)b*NPOINT + (it - 31) + lane)*3;
                o[0] = rx; o[1] = ry; o[2] = rz;
            }
        }
    }
}

// ---------------- ball query: smem-staged, 32 queries per 1024-thr CTA -------
__global__ __launch_bounds__(1024,2) void k_ballquery(const float* __restrict__ xyz,
                                                      const float* __restrict__ newxyz) {
    extern __shared__ float sm[];
    float* sx = sm;
    float* sy = sm + 8192;
    float* sz = sm + 16384;
    int tid = threadIdx.x;
    int b = blockIdx.x >> 6;
    int qbase = (blockIdx.x & 63) * 32;

    const float* xb = xyz + (size_t)b*NN*3;
    for (int p = tid; p < NN; p += 1024) {
        sx[p] = xb[3*p+0];
        sy[p] = xb[3*p+1];
        sz[p] = xb[3*p+2];
    }
    __syncthreads();

    int w = tid >> 5, lane = tid & 31;
    int s = qbase + w;
    int gq = b*NPOINT + s;
    const float* np = newxyz + (size_t)gq*3;
    float qx = np[0], qy = np[1], qz = np[2];
    int* outp = d_ball_idx + (size_t)gq*NSAMPLE;

    int cnt = 0, firstIdx = 0; bool haveFirst = false;
    for (int j0 = 0; j0 < NN && cnt < NSAMPLE; j0 += 32) {
        int j = j0 + lane;
        float dx = __fadd_rn(sx[j], -qx);
        float dy = __fadd_rn(sy[j], -qy);
        float dz = __fadd_rn(sz[j], -qz);
        float d = __fadd_rn(__fadd_rn(__fmul_rn(dx,dx), __fmul_rn(dy,dy)),
                            __fmul_rn(dz,dz));
        bool in = d < RADIUS2;
        unsigned mm = __ballot_sync(0xffffffffu, in);
        if (mm) {
            if (!haveFirst) { firstIdx = j0 + __ffs(mm) - 1; haveFirst = true; }
            if (in) {
                int pos = cnt + __popc(mm & ((1u << lane) - 1u));
                if (pos < NSAMPLE) outp[pos] = j;
            }
            cnt += __popc(mm);
        }
    }
    int fs = cnt < NSAMPLE ? cnt : NSAMPLE;
    for (int pos = fs + lane; pos < NSAMPLE; pos += 32) outp[pos] = firstIdx;
}

// ======== packed-FMA 8x8 micro-kernel (R6/R9 form — best measured) ============
#define MM8x8_K(sw_row, sg_row)                                               \
    do {                                                                      \
        float wv[8], g[8];                                                    \
        *(float4*)&wv[0] = *(const float4*)&(sw_row)[0];                      \
        *(float4*)&wv[4] = *(const float4*)&(sw_row)[4];                      \
        *(float4*)&g[0]  = *(const float4*)&(sg_row)[0];                      \
        *(float4*)&g[4]  = *(const float4*)&(sg_row)[4];                      \
        unsigned long long g2[4];                                             \
        PACK2(g2[0], g[0], g[1]); PACK2(g2[1], g[2], g[3]);                   \
        PACK2(g2[2], g[4], g[5]); PACK2(g2[3], g[6], g[7]);                   \
        _Pragma("unroll")                                                     \
        for (int i = 0; i < 8; i++) {                                         \
            unsigned long long w2; PACK2(w2, wv[i], wv[i]);                   \
            FMA2(acc2[i][0], w2, g2[0], acc2[i][0]);                          \
            FMA2(acc2[i][1], w2, g2[1], acc2[i][1]);                          \
            FMA2(acc2[i][2], w2, g2[2], acc2[i][2]);                          \
            FMA2(acc2[i][3], w2, g2[3], acc2[i][3]);                          \
        }                                                                     \
    } while (0)

// ---------------- layer 1: gather + GEMM(64x67) + stat partials --------------
__global__ __launch_bounds__(256,2) void k_layer1(const float* __restrict__ xyz,
                                                  const float* __restrict__ newxyz,
                                                  const float* __restrict__ W1) {
    extern __shared__ float sm[];
    float (*sg)[256] = (float(*)[256])sm;              // 67 x 256
    float (*sw)[64]  = (float(*)[64])(sm + 67*256);    // 67 x 64
    int tid = threadIdx.x;
    int pos0 = blockIdx.x * 256;

    for (int i = tid; i < 64*67; i += 256) { int o = i/67, c = i%67; sw[c][o] = W1[i]; }
    {
        int pos = pos0 + tid;
        int idx = d_ball_idx[pos];
        int b = pos >> 16;
        int s = (pos >> 5) & 2047;
        const float* nx = newxyz + ((size_t)b*NPOINT + s)*3;
        const float* pp = xyz + ((size_t)b*NN + idx)*3;
        sg[0][tid] = pp[0]-nx[0];
        sg[1][tid] = pp[1]-nx[1];
        sg[2][tid] = pp[2]-nx[2];
        const float4* fr = (const float4*)(d_featT + ((size_t)b*NN + idx)*CC);
#pragma unroll
        for (int c4 = 0; c4 < 16; c4++) {
            float4 v = fr[c4];
            sg[3+c4*4+0][tid] = v.x; sg[3+c4*4+1][tid] = v.y;
            sg[3+c4*4+2][tid] = v.z; sg[3+c4*4+3][tid] = v.w;
        }
    }
    __syncthreads();

    int tr = tid >> 5, tc = tid & 31;
    unsigned long long acc2[8][4];
#pragma unroll
    for (int i=0;i<8;i++)
#pragma unroll
        for (int j=0;j<4;j++) acc2[i][j]=0ull;

#pragma unroll 2
    for (int k = 0; k < 67; k++)
        MM8x8_K(&sw[k][tr*8], &sg[k][tc*8]);

    float acc[8][8];
#pragma unroll
    for (int i=0;i<8;i++)
#pragma unroll
        for (int j=0;j<4;j++) UNPACK2(acc[i][2*j], acc[i][2*j+1], acc2[i][j]);

#pragma unroll
    for (int i = 0; i < 8; i++) {
        int c = tr*8 + i;
        float* hp = d_h1 + (size_t)c*P_TOTAL + pos0 + tc*8;
        *(float4*)hp     = make_float4(acc[i][0],acc[i][1],acc[i][2],acc[i][3]);
        *(float4*)(hp+4) = make_float4(acc[i][4],acc[i][5],acc[i][6],acc[i][7]);
    }
#pragma unroll
    for (int i = 0; i < 8; i++) {
        float s = 0.f, q = 0.f;
#pragma unroll
        for (int j = 0; j < 8; j++) { s += acc[i][j]; q += acc[i][j]*acc[i][j]; }
#pragma unroll
        for (int o = 16; o > 0; o >>= 1) {
            s += __shfl_xor_sync(0xffffffffu, s, o);
            q += __shfl_xor_sync(0xffffffffu, q, o);
        }
        if (tc == 0) {
            int c = tr*8 + i;
            d_partials[((size_t)blockIdx.x*128 + c)*2 + 0] = s;
            d_partials[((size_t)blockIdx.x*128 + c)*2 + 1] = q;
        }
    }
}

// ---------------- deterministic stats reduce + BN fold -----------------------
__global__ void k_stats(const float* __restrict__ gam, const float* __restrict__ bet,
                        int nblocks) {
    int c = blockIdx.x, t = threadIdx.x;
    double s = 0.0, q = 0.0;
    for (int i = t; i < nblocks; i += 256) {
        s += (double)d_partials[((size_t)i*128 + c)*2 + 0];
        q += (double)d_partials[((size_t)i*128 + c)*2 + 1];
    }
    __shared__ double ss[256], qq[256];
    ss[t] = s; qq[t] = q; __syncthreads();
    for (int o = 128; o > 0; o >>= 1) {
        if (t < o) { ss[t] += ss[t+o]; qq[t] += qq[t+o]; }
        __syncthreads();
    }
    if (t == 0) {
        double mu  = ss[0] / (double)P_TOTAL;
        double var = qq[0] / (double)P_TOTAL - mu*mu;
        float a  = (float)((double)gam[c] / sqrt(var + 1e-5));
        float bp = (float)((double)bet[c] - mu * (double)a);
        d_ab[c*2] = a; d_ab[c*2+1] = bp;
    }
}

// ---------------- layer 2: bn1+relu on load, GEMM(64x64) ---------------------
__global__ __launch_bounds__(256,2) void k_layer2(const float* __restrict__ W2) {
    extern __shared__ float sm[];
    float (*sg)[256] = (float(*)[256])sm;              // 64 x 256
    float (*sw)[64]  = (float(*)[64])(sm + 64*256);    // 64 x 64
    int tid = threadIdx.x;
    int pos0 = blockIdx.x * 256;
    int wid = tid >> 5, lane = tid & 31;

    for (int i = tid; i < 64*64; i += 256) { int o = i/64, c = i%64; sw[c][o] = W2[i]; }
    for (int c = wid; c < 64; c += 8) {
        float a = d_ab[c*2], bp = d_ab[c*2+1];
        const float4* src = (const float4*)(d_h1 + (size_t)c*P_TOTAL + pos0) + lane*2;
        float4 v0 = src[0], v1 = src[1];
        v0.x=fmaxf(0.f,a*v0.x+bp); v0.y=fmaxf(0.f,a*v0.y+bp);
        v0.z=fmaxf(0.f,a*v0.z+bp); v0.w=fmaxf(0.f,a*v0.w+bp);
        v1.x=fmaxf(0.f,a*v1.x+bp); v1.y=fmaxf(0.f,a*v1.y+bp);
        v1.z=fmaxf(0.f,a*v1.z+bp); v1.w=fmaxf(0.f,a*v1.w+bp);
        *(float4*)&sg[c][lane*8]   = v0;
        *(float4*)&sg[c][lane*8+4] = v1;
    }
    __syncthreads();

    int tr = wid, tc = lane;
    unsigned long long acc2[8][4];
#pragma unroll
    for (int i=0;i<8;i++)
#pragma unroll
        for (int j=0;j<4;j++) acc2[i][j]=0ull;

#pragma unroll 2
    for (int k = 0; k < 64; k++)
        MM8x8_K(&sw[k][tr*8], &sg[k][tc*8]);

    float acc[8][8];
#pragma unroll
    for (int i=0;i<8;i++)
#pragma unroll
        for (int j=0;j<4;j++) UNPACK2(acc[i][2*j], acc[i][2*j+1], acc2[i][j]);

#pragma unroll
    for (int i = 0; i < 8; i++) {
        int c = tr*8 + i;
        float* hp = d_h2 + (size_t)c*P_TOTAL + pos0 + tc*8;
        *(float4*)hp     = make_float4(acc[i][0],acc[i][1],acc[i][2],acc[i][3]);
        *(float4*)(hp+4) = make_float4(acc[i][4],acc[i][5],acc[i][6],acc[i][7]);
    }
#pragma unroll
    for (int i = 0; i < 8; i++) {
        float s = 0.f, q = 0.f;
#pragma unroll
        for (int j = 0; j < 8; j++) { s += acc[i][j]; q += acc[i][j]*acc[i][j]; }
#pragma unroll
        for (int o = 16; o > 0; o >>= 1) {
            s += __shfl_xor_sync(0xffffffffu, s, o);
            q += __shfl_xor_sync(0xffffffffu, q, o);
        }
        if (tc == 0) {
            int c = tr*8 + i;
            d_partials[((size_t)blockIdx.x*128 + c)*2 + 0] = s;
            d_partials[((size_t)blockIdx.x*128 + c)*2 + 1] = q;
        }
    }
}

// ---------------- layer 3: bn2+relu on load, GEMM(128x64), fused max/min -----
__global__ __launch_bounds__(256,2) void k_layer3(const float* __restrict__ W3) {
    extern __shared__ float sm[];
    float (*sg)[128] = (float(*)[128])sm;              // 64 x 128
    float (*sw)[128] = (float(*)[128])(sm + 64*128);   // 64 x 128
    int tid = threadIdx.x;
    int pos0 = blockIdx.x * 128;
    int wid = tid >> 5, lane = tid & 31;

    for (int i = tid; i < 128*64; i += 256) { int o = i/64, c = i%64; sw[c][o] = W3[i]; }
    for (int c = wid; c < 64; c += 8) {
        float a = d_ab[c*2], bp = d_ab[c*2+1];
        const float4* src = (const float4*)(d_h2 + (size_t)c*P_TOTAL + pos0);
        float4 v = src[lane];
        v.x=fmaxf(0.f,a*v.x+bp); v.y=fmaxf(0.f,a*v.y+bp);
        v.z=fmaxf(0.f,a*v.z+bp); v.w=fmaxf(0.f,a*v.w+bp);
        *(float4*)&sg[c][lane*4] = v;
    }
    __syncthreads();

    int tr = tid >> 4, tc = tid & 15;
    unsigned long long acc2[8][4];
#pragma unroll
    for (int i=0;i<8;i++)
#pragma unroll
        for (int j=0;j<4;j++) acc2[i][j]=0ull;

#pragma unroll 2
    for (int k = 0; k < 64; k++)
        MM8x8_K(&sw[k][tr*8], &sg[k][tc*8]);

    float acc[8][8];
#pragma unroll
    for (int i=0;i<8;i++)
#pragma unroll
        for (int j=0;j<4;j++) UNPACK2(acc[i][2*j], acc[i][2*j+1], acc2[i][j]);

    int sglob = (pos0 >> 5) + (tc >> 2);
#pragma unroll
    for (int i = 0; i < 8; i++) {
        int c = tr*8 + i;
        float mx = acc[i][0], mn = acc[i][0];
#pragma unroll
        for (int j = 1; j < 8; j++) { mx = fmaxf(mx, acc[i][j]); mn = fminf(mn, acc[i][j]); }
        mx = fmaxf(mx, __shfl_xor_sync(0xffffffffu, mx, 1));
        mn = fminf(mn, __shfl_xor_sync(0xffffffffu, mn, 1));
        mx = fmaxf(mx, __shfl_xor_sync(0xffffffffu, mx, 2));
        mn = fminf(mn, __shfl_xor_sync(0xffffffffu, mn, 2));
        if ((tc & 3) == 0) {
            d_hmx[(size_t)c*(BB*NPOINT) + sglob] = mx;
            d_hmn[(size_t)c*(BB*NPOINT) + sglob] = mn;
        }
    }
#pragma unroll
    for (int i = 0; i < 8; i++) {
        float s = 0.f, q = 0.f;
#pragma unroll
        for (int j = 0; j < 8; j++) { s += acc[i][j]; q += acc[i][j]*acc[i][j]; }
#pragma unroll
        for (int o = 8; o > 0; o >>= 1) {
            s += __shfl_xor_sync(0xffffffffu, s, o);
            q += __shfl_xor_sync(0xffffffffu, q, o);
        }
        if (tc == 0) {
            int c = tr*8 + i;
            d_partials[((size_t)blockIdx.x*128 + c)*2 + 0] = s;
            d_partials[((size_t)blockIdx.x*128 + c)*2 + 1] = q;
        }
    }
}

// ---------------- bn3 + relu on the pooled extremum --------------------------
__global__ void k_finalize(float* __restrict__ feats) {
    int gid = blockIdx.x*blockDim.x + threadIdx.x;
    if (gid >= BB*128*NPOINT) return;
    int s = gid & 2047;
    int o = (gid >> 11) & 127;
    int b = gid >> 18;
    float a = d_ab[o*2], bp = d_ab[o*2+1];
    size_t ix = (size_t)o*(BB*NPOINT) + b*NPOINT + s;
    float v = (a >= 0.0f) ? d_hmx[ix] : d_hmn[ix];
    feats[gid] = fmaxf(0.0f, a*v + bp);
}

// ---------------- launch ------------------------------------------------------
extern "C" void kernel_launch(void* const* d_in, const int* in_sizes, int n_in,
                              void* d_out, int out_size) {
    const float* xyz      = (const float*)d_in[0];
    const float* features = (const float*)d_in[1];
    const float* W1 = (const float*)d_in[2];
    const float* g1 = (const float*)d_in[3];
    const float* b1 = (const float*)d_in[4];
    const float* W2 = (const float*)d_in[5];
    const float* g2 = (const float*)d_in[6];
    const float* b2 = (const float*)d_in[7];
    const float* W3 = (const float*)d_in[8];
    const float* g3 = (const float*)d_in[9];
    const float* b3 = (const float*)d_in[10];
    float* out    = (float*)d_out;
    float* newxyz = out;                       // 8*2048*3
    float* feats  = out + BB*NPOINT*3;         // 8*128*2048

    const int SMF = NN*16;                     // 128KB float4 point cache
    const int SMQ = 3*NN*4;                    // 96KB ballquery stage
    const int SM1 = (67*256 + 67*64) * 4;      // 85760
    const int SM2 = (64*256 + 64*64) * 4;      // 81920
    const int SM3 = (64*128 + 64*128) * 4;     // 65536
    cudaFuncSetAttribute(k_fps,       cudaFuncAttributeMaxDynamicSharedMemorySize, SMF);
    cudaFuncSetAttribute(k_ballquery, cudaFuncAttributeMaxDynamicSharedMemorySize, SMQ);
    cudaFuncSetAttribute(k_layer1,    cudaFuncAttributeMaxDynamicSharedMemorySize, SM1);
    cudaFuncSetAttribute(k_layer2,    cudaFuncAttributeMaxDynamicSharedMemorySize, SM2);
    cudaFuncSetAttribute(k_layer3,    cudaFuncAttributeMaxDynamicSharedMemorySize, SM3);

    k_transpose<<<dim3(NN/32, CC/32, BB), dim3(32,8)>>>(features);
    k_sort<<<BB, 1024>>>(xyz);
    k_fps<<<BB, 1024, SMF>>>(xyz, newxyz);
    k_ballquery<<<BB*64, 1024, SMQ>>>(xyz, newxyz);

    k_layer1<<<P_TOTAL/256, 256, SM1>>>(xyz, newxyz, W1);
    k_stats<<<64, 256>>>(g1, b1, P_TOTAL/256);
    k_layer2<<<P_TOTAL/256, 256, SM2>>>(W2);
    k_stats<<<64, 256>>>(g2, b2, P_TOTAL/256);
    k_layer3<<<P_TOTAL/128, 256, SM3>>>(W3);
    k_stats<<<128, 256>>>(g3, b3, P_TOTAL/128);
    k_finalize<<<(BB*128*NPOINT)/256, 256>>>(feats);
}

// round 13
// speedup vs baseline: 1.5386x; 1.0697x over previous
#include <cuda_runtime.h>
#include <stdint.h>

#define BB 8
#define NN 8192
#define CC 64
#define NPOINT 2048
#define NSAMPLE 32
#define RADIUS2 0.04f
#define P_TOTAL (BB*NPOINT*NSAMPLE)   // 524288

// ---------------- scratch (device globals; no allocation allowed) ------------
__device__ float d_featT[BB*NN*CC];                 // 16.8 MB  (B,N,C)
__device__ int   d_ball_idx[P_TOTAL];
__device__ float d_h1[(size_t)64*P_TOTAL];          // 134 MB
__device__ float d_h2[(size_t)64*P_TOTAL];          // 134 MB
__device__ float d_hmx[(size_t)128*BB*NPOINT];      // 8 MB
__device__ float d_hmn[(size_t)128*BB*NPOINT];      // 8 MB
__device__ float d_partials[4096*128*2];            // 4 MB
__device__ float d_ab[128*2];                       // fused BN scale/shift
// Morton-sorted copies of xyz (+ original index)
__device__ float d_sx[BB*NN], d_sy[BB*NN], d_sz[BB*NN];
__device__ int   d_sidx[BB*NN];

// ---------------- packed f32x2 helpers (exact per-element RN) ----------------
#define PACK2(out, lo, hi)  asm("mov.b64 %0, {%1, %2};" : "=l"(out) : "f"(lo), "f"(hi))
#define UNPACK2(lo, hi, in) asm("mov.b64 {%0, %1}, %2;" : "=f"(lo), "=f"(hi) : "l"(in))
#define ADD2(out, a, b)     asm("add.rn.f32x2 %0, %1, %2;" : "=l"(out) : "l"(a), "l"(b))
#define MUL2(out, a, b)     asm("mul.rn.f32x2 %0, %1, %2;" : "=l"(out) : "l"(a), "l"(b))
#define FMA2(d, a, b, c)    asm("fma.rn.f32x2 %0, %1, %2, %3;" : "=l"(d) : "l"(a), "l"(b), "l"(c))

// ---------------- feature transpose (B,C,N) -> (B,N,C) -----------------------
__global__ void k_transpose(const float* __restrict__ f) {
    __shared__ float tile[32][33];
    int b = blockIdx.z, n0 = blockIdx.x*32, c0 = blockIdx.y*32;
    int tx = threadIdx.x, ty = threadIdx.y;
    for (int i = ty; i < 32; i += 8)
        tile[i][tx] = f[((size_t)b*CC + c0 + i)*NN + n0 + tx];
    __syncthreads();
    for (int i = ty; i < 32; i += 8)
        d_featT[((size_t)b*NN + n0 + i)*CC + c0 + tx] = tile[tx][i];
}

// ---------------- Morton counting sort: one CTA per batch --------------------
__global__ __launch_bounds__(1024,1) void k_sort(const float* __restrict__ xyz) {
    __shared__ int cnt[4096];
    __shared__ unsigned short cell[8192];
    __shared__ int wsum[32];
    int b = blockIdx.x, t = threadIdx.x;
    for (int i = t; i < 4096; i += 1024) cnt[i] = 0;
    __syncthreads();
    const float* xb = xyz + (size_t)b*NN*3;
    for (int i = t; i < NN; i += 1024) {
        float x = xb[i*3+0], y = xb[i*3+1], z = xb[i*3+2];
        int cx = min(15, max(0, (int)(x*16.0f)));
        int cy = min(15, max(0, (int)(y*16.0f)));
        int cz = min(15, max(0, (int)(z*16.0f)));
        int m = 0;
#pragma unroll
        for (int j = 0; j < 4; j++)
            m |= (((cx>>j)&1)<<(3*j)) | (((cy>>j)&1)<<(3*j+1)) | (((cz>>j)&1)<<(3*j+2));
        cell[i] = (unsigned short)m;
        atomicAdd(&cnt[m], 1);
    }
    __syncthreads();
    int c0 = cnt[t*4+0], c1 = cnt[t*4+1], c2 = cnt[t*4+2], c3 = cnt[t*4+3];
    int ts = c0+c1+c2+c3;
    int lane = t & 31, w = t >> 5;
    int x = ts;
#pragma unroll
    for (int o = 1; o < 32; o <<= 1) {
        int y = __shfl_up_sync(0xffffffffu, x, o);
        if (lane >= o) x += y;
    }
    if (lane == 31) wsum[w] = x;
    int wex = x - ts;
    __syncthreads();
    if (w == 0) {
        int v = wsum[lane];
        int xx = v;
#pragma unroll
        for (int o = 1; o < 32; o <<= 1) {
            int y = __shfl_up_sync(0xffffffffu, xx, o);
            if (lane >= o) xx += y;
        }
        wsum[lane] = xx - v;
    }
    __syncthreads();
    int basep = wsum[w] + wex;
    cnt[t*4+0] = basep;
    cnt[t*4+1] = basep + c0;
    cnt[t*4+2] = basep + c0 + c1;
    cnt[t*4+3] = basep + c0 + c1 + c2;
    __syncthreads();
    for (int i = t; i < NN; i += 1024) {
        int m = cell[i];
        int pos = atomicAdd(&cnt[m], 1);
        d_sx[b*NN+pos] = xb[i*3+0];
        d_sy[b*NN+pos] = xb[i*3+1];
        d_sz[b*NN+pos] = xb[i*3+2];
        d_sidx[b*NN+pos] = i;
    }
}

// ---------------- FPS: 1 CTA/batch, 1024 thr, 32 warps x 256 pts (R9 form) ---
__global__ __launch_bounds__(1024,1) void k_fps(const float* __restrict__ xyz,
                                                float* __restrict__ out_newxyz) {
    extern __shared__ float smem[];
    float* s_px = smem;
    float* s_py = smem + 8192;
    float* s_pz = smem + 16384;
    __shared__ unsigned s_val[2][32];
    __shared__ unsigned s_key[2][32];

    const int b = blockIdx.x, tid = threadIdx.x;
    const int w = tid >> 5, lane = tid & 31;
    const int base = w*256 + lane*8;

    float X[8], Y[8], Z[8], dd[8];
    unsigned OIK[8];
    {
        const float* sx = d_sx + b*NN;
        const float* sy = d_sy + b*NN;
        const float* sz = d_sz + b*NN;
        const int*   si = d_sidx + b*NN;
#pragma unroll
        for (int q = 0; q < 2; q++) {
            float4 vx = *(const float4*)(sx + base + q*4);
            float4 vy = *(const float4*)(sy + base + q*4);
            float4 vz = *(const float4*)(sz + base + q*4);
            int4   vi = *(const int4*)  (si + base + q*4);
            X[q*4+0]=vx.x; X[q*4+1]=vx.y; X[q*4+2]=vx.z; X[q*4+3]=vx.w;
            Y[q*4+0]=vy.x; Y[q*4+1]=vy.y; Y[q*4+2]=vy.z; Y[q*4+3]=vy.w;
            Z[q*4+0]=vz.x; Z[q*4+1]=vz.y; Z[q*4+2]=vz.z; Z[q*4+3]=vz.w;
            OIK[q*4+0]=((unsigned)vi.x<<13)|(unsigned)(base+q*4+0);
            OIK[q*4+1]=((unsigned)vi.y<<13)|(unsigned)(base+q*4+1);
            OIK[q*4+2]=((unsigned)vi.z<<13)|(unsigned)(base+q*4+2);
            OIK[q*4+3]=((unsigned)vi.w<<13)|(unsigned)(base+q*4+3);
        }
#pragma unroll
        for (int i = 0; i < 8; i++) {
            s_px[base+i]=X[i]; s_py[base+i]=Y[i]; s_pz[base+i]=Z[i];
            dd[i]=1e10f;
        }
    }
    float bxn=X[0],bxx=X[0],byn=Y[0],byx=Y[0],bzn=Z[0],bzx=Z[0];
#pragma unroll
    for (int i = 1; i < 8; i++) {
        bxn=fminf(bxn,X[i]); bxx=fmaxf(bxx,X[i]);
        byn=fminf(byn,Y[i]); byx=fmaxf(byx,Y[i]);
        bzn=fminf(bzn,Z[i]); bzx=fmaxf(bzx,Z[i]);
    }
#pragma unroll
    for (int o = 16; o >= 1; o >>= 1) {
        bxn=fminf(bxn,__shfl_xor_sync(0xffffffffu,bxn,o));
        bxx=fmaxf(bxx,__shfl_xor_sync(0xffffffffu,bxx,o));
        byn=fminf(byn,__shfl_xor_sync(0xffffffffu,byn,o));
        byx=fmaxf(byx,__shfl_xor_sync(0xffffffffu,byx,o));
        bzn=fminf(bzn,__shfl_xor_sync(0xffffffffu,bzn,o));
        bzx=fmaxf(bzx,__shfl_xor_sync(0xffffffffu,bzx,o));
    }
    unsigned long long PX[4],PY[4],PZ[4];
#pragma unroll
    for (int j = 0; j < 4; j++) {
        PACK2(PX[j],X[2*j],X[2*j+1]);
        PACK2(PY[j],Y[2*j],Y[2*j+1]);
        PACK2(PZ[j],Z[2*j],Z[2*j+1]);
    }
    unsigned wmax = __float_as_uint(1e10f), wkey = 0xffffffffu;

    float lx, ly, lz;
    {
        const float* xb = xyz + (size_t)b*NN*3;
        lx = xb[0]; ly = xb[1]; lz = xb[2];
    }
    if (tid == 0) {
        float* o = out_newxyz + (size_t)b*NPOINT*3;
        o[0] = lx; o[1] = ly; o[2] = lz;
    }

    for (int it = 1; it < NPOINT; it++) {
        const int par = it & 1;
        float dxl = fmaxf(fmaxf(__fadd_rn(bxn,-lx), __fadd_rn(lx,-bxx)), 0.0f);
        float dyl = fmaxf(fmaxf(__fadd_rn(byn,-ly), __fadd_rn(ly,-byx)), 0.0f);
        float dzl = fmaxf(fmaxf(__fadd_rn(bzn,-lz), __fadd_rn(lz,-bzx)), 0.0f);
        float dlb = (dxl*dxl + dyl*dyl + dzl*dzl) * 0.9999f;
        if (dlb < __uint_as_float(wmax)) {
            float nlx = -lx, nly = -ly, nlz = -lz;
            unsigned long long NLX, NLY, NLZ;
            PACK2(NLX,nlx,nlx); PACK2(NLY,nly,nly); PACK2(NLZ,nlz,nlz);
            float lv = 0.0f;
#pragma unroll
            for (int j = 0; j < 4; j++) {
                unsigned long long dx,dy,dz,qx,qy,qz,t,s;
                ADD2(dx,PX[j],NLX); ADD2(dy,PY[j],NLY); ADD2(dz,PZ[j],NLZ);
                MUL2(qx,dx,dx); MUL2(qy,dy,dy); MUL2(qz,dz,dz);
                ADD2(t,qx,qy); ADD2(s,t,qz);
                float da,db; UNPACK2(da,db,s);
                dd[2*j]   = fminf(dd[2*j],da);
                dd[2*j+1] = fminf(dd[2*j+1],db);
                lv = fmaxf(lv, fmaxf(dd[2*j], dd[2*j+1]));
            }
            wmax = __reduce_max_sync(0xffffffffu, __float_as_uint(lv));
            unsigned cand = 0xffffffffu;
            if (__float_as_uint(lv) == wmax) {
#pragma unroll
                for (int i = 0; i < 8; i++)
                    if (__float_as_uint(dd[i]) == wmax) cand = min(cand, OIK[i]);
            }
            wkey = __reduce_min_sync(0xffffffffu, cand);
        }
        if (lane == 0) { s_val[par][w] = wmax; s_key[par][w] = wkey; }
        __syncthreads();
        unsigned v  = s_val[par][lane];
        unsigned m  = __reduce_max_sync(0xffffffffu, v);
        unsigned ck = (v == m) ? s_key[par][lane] : 0xffffffffu;
        unsigned gk = __reduce_min_sync(0xffffffffu, ck);
        int p = (int)(gk & 8191u);
        lx = s_px[p]; ly = s_py[p]; lz = s_pz[p];
        if (tid == 0) {
            float* o2 = out_newxyz + ((size_t)b*NPOINT + it)*3;
            o2[0] = lx; o2[1] = ly; o2[2] = lz;
        }
    }
}

// ---------------- ball query: smem-staged, 32 queries per 1024-thr CTA -------
__global__ __launch_bounds__(1024,2) void k_ballquery(const float* __restrict__ xyz,
                                                      const float* __restrict__ newxyz) {
    extern __shared__ float sm[];
    float* sx = sm;
    float* sy = sm + 8192;
    float* sz = sm + 16384;
    int tid = threadIdx.x;
    int b = blockIdx.x >> 6;
    int qbase = (blockIdx.x & 63) * 32;

    const float* xb = xyz + (size_t)b*NN*3;
    for (int p = tid; p < NN; p += 1024) {
        sx[p] = xb[3*p+0];
        sy[p] = xb[3*p+1];
        sz[p] = xb[3*p+2];
    }
    __syncthreads();

    int w = tid >> 5, lane = tid & 31;
    int s = qbase + w;
    int gq = b*NPOINT + s;
    const float* np = newxyz + (size_t)gq*3;
    float qx = np[0], qy = np[1], qz = np[2];
    int* outp = d_ball_idx + (size_t)gq*NSAMPLE;

    int cnt = 0, firstIdx = 0; bool haveFirst = false;
    for (int j0 = 0; j0 < NN && cnt < NSAMPLE; j0 += 32) {
        int j = j0 + lane;
        float dx = __fadd_rn(sx[j], -qx);
        float dy = __fadd_rn(sy[j], -qy);
        float dz = __fadd_rn(sz[j], -qz);
        float d = __fadd_rn(__fadd_rn(__fmul_rn(dx,dx), __fmul_rn(dy,dy)),
                            __fmul_rn(dz,dz));
        bool in = d < RADIUS2;
        unsigned mm = __ballot_sync(0xffffffffu, in);
        if (mm) {
            if (!haveFirst) { firstIdx = j0 + __ffs(mm) - 1; haveFirst = true; }
            if (in) {
                int pos = cnt + __popc(mm & ((1u << lane) - 1u));
                if (pos < NSAMPLE) outp[pos] = j;
            }
            cnt += __popc(mm);
        }
    }
    int fs = cnt < NSAMPLE ? cnt : NSAMPLE;
    for (int pos = fs + lane; pos < NSAMPLE; pos += 32) outp[pos] = firstIdx;
}

// ======== packed-FMA 8x8 micro-kernel (best measured) =========================
#define MM8x8_K(sw_row, sg_row)                                               \
    do {                                                                      \
        float wv[8], g[8];                                                    \
        *(float4*)&wv[0] = *(const float4*)&(sw_row)[0];                      \
        *(float4*)&wv[4] = *(const float4*)&(sw_row)[4];                      \
        *(float4*)&g[0]  = *(const float4*)&(sg_row)[0];                      \
        *(float4*)&g[4]  = *(const float4*)&(sg_row)[4];                      \
        unsigned long long g2[4];                                             \
        PACK2(g2[0], g[0], g[1]); PACK2(g2[1], g[2], g[3]);                   \
        PACK2(g2[2], g[4], g[5]); PACK2(g2[3], g[6], g[7]);                   \
        _Pragma("unroll")                                                     \
        for (int i = 0; i < 8; i++) {                                         \
            unsigned long long w2; PACK2(w2, wv[i], wv[i]);                   \
            FMA2(acc2[i][0], w2, g2[0], acc2[i][0]);                          \
            FMA2(acc2[i][1], w2, g2[1], acc2[i][1]);                          \
            FMA2(acc2[i][2], w2, g2[2], acc2[i][2]);                          \
            FMA2(acc2[i][3], w2, g2[3], acc2[i][3]);                          \
        }                                                                     \
    } while (0)

// ---------------- layer 1: gather + GEMM(64x67) + stat partials --------------
__global__ __launch_bounds__(256,2) void k_layer1(const float* __restrict__ xyz,
                                                  const float* __restrict__ newxyz,
                                                  const float* __restrict__ W1) {
    extern __shared__ float sm[];
    float (*sg)[256] = (float(*)[256])sm;              // 67 x 256
    float (*sw)[64]  = (float(*)[64])(sm + 67*256);    // 67 x 64
    int tid = threadIdx.x;
    int pos0 = blockIdx.x * 256;

    for (int i = tid; i < 64*67; i += 256) { int o = i/67, c = i%67; sw[c][o] = W1[i]; }
    {
        int pos = pos0 + tid;
        int idx = d_ball_idx[pos];
        int b = pos >> 16;
        int s = (pos >> 5) & 2047;
        const float* nx = newxyz + ((size_t)b*NPOINT + s)*3;
        const float* pp = xyz + ((size_t)b*NN + idx)*3;
        sg[0][tid] = pp[0]-nx[0];
        sg[1][tid] = pp[1]-nx[1];
        sg[2][tid] = pp[2]-nx[2];
        const float4* fr = (const float4*)(d_featT + ((size_t)b*NN + idx)*CC);
#pragma unroll
        for (int c4 = 0; c4 < 16; c4++) {
            float4 v = fr[c4];
            sg[3+c4*4+0][tid] = v.x; sg[3+c4*4+1][tid] = v.y;
            sg[3+c4*4+2][tid] = v.z; sg[3+c4*4+3][tid] = v.w;
        }
    }
    __syncthreads();

    int tr = tid >> 5, tc = tid & 31;
    unsigned long long acc2[8][4];
#pragma unroll
    for (int i=0;i<8;i++)
#pragma unroll
        for (int j=0;j<4;j++) acc2[i][j]=0ull;

#pragma unroll 2
    for (int k = 0; k < 67; k++)
        MM8x8_K(&sw[k][tr*8], &sg[k][tc*8]);

    float acc[8][8];
#pragma unroll
    for (int i=0;i<8;i++)
#pragma unroll
        for (int j=0;j<4;j++) UNPACK2(acc[i][2*j], acc[i][2*j+1], acc2[i][j]);

#pragma unroll
    for (int i = 0; i < 8; i++) {
        int c = tr*8 + i;
        float* hp = d_h1 + (size_t)c*P_TOTAL + pos0 + tc*8;
        *(float4*)hp     = make_float4(acc[i][0],acc[i][1],acc[i][2],acc[i][3]);
        *(float4*)(hp+4) = make_float4(acc[i][4],acc[i][5],acc[i][6],acc[i][7]);
    }
#pragma unroll
    for (int i = 0; i < 8; i++) {
        float s = 0.f, q = 0.f;
#pragma unroll
        for (int j = 0; j < 8; j++) { s += acc[i][j]; q += acc[i][j]*acc[i][j]; }
#pragma unroll
        for (int o = 16; o > 0; o >>= 1) {
            s += __shfl_xor_sync(0xffffffffu, s, o);
            q += __shfl_xor_sync(0xffffffffu, q, o);
        }
        if (tc == 0) {
            int c = tr*8 + i;
            d_partials[((size_t)blockIdx.x*128 + c)*2 + 0] = s;
            d_partials[((size_t)blockIdx.x*128 + c)*2 + 1] = q;
        }
    }
}

// ---------------- deterministic stats reduce + BN fold -----------------------
__global__ void k_stats(const float* __restrict__ gam, const float* __restrict__ bet,
                        int nblocks) {
    int c = blockIdx.x, t = threadIdx.x;
    double s = 0.0, q = 0.0;
    for (int i = t; i < nblocks; i += 256) {
        s += (double)d_partials[((size_t)i*128 + c)*2 + 0];
        q += (double)d_partials[((size_t)i*128 + c)*2 + 1];
    }
    __shared__ double ss[256], qq[256];
    ss[t] = s; qq[t] = q; __syncthreads();
    for (int o = 128; o > 0; o >>= 1) {
        if (t < o) { ss[t] += ss[t+o]; qq[t] += qq[t+o]; }
        __syncthreads();
    }
    if (t == 0) {
        double mu  = ss[0] / (double)P_TOTAL;
        double var = qq[0] / (double)P_TOTAL - mu*mu;
        float a  = (float)((double)gam[c] / sqrt(var + 1e-5));
        float bp = (float)((double)bet[c] - mu * (double)a);
        d_ab[c*2] = a; d_ab[c*2+1] = bp;
    }
}

// ---------------- layer 2: bn1+relu on load, GEMM(64x64) ---------------------
__global__ __launch_bounds__(256,2) void k_layer2(const float* __restrict__ W2) {
    extern __shared__ float sm[];
    float (*sg)[256] = (float(*)[256])sm;              // 64 x 256
    float (*sw)[64]  = (float(*)[64])(sm + 64*256);    // 64 x 64
    int tid = threadIdx.x;
    int pos0 = blockIdx.x * 256;
    int wid = tid >> 5, lane = tid & 31;

    for (int i = tid; i < 64*64; i += 256) { int o = i/64, c = i%64; sw[c][o] = W2[i]; }
    for (int c = wid; c < 64; c += 8) {
        float a = d_ab[c*2], bp = d_ab[c*2+1];
        const float4* src = (const float4*)(d_h1 + (size_t)c*P_TOTAL + pos0) + lane*2;
        float4 v0 = src[0], v1 = src[1];
        v0.x=fmaxf(0.f,a*v0.x+bp); v0.y=fmaxf(0.f,a*v0.y+bp);
        v0.z=fmaxf(0.f,a*v0.z+bp); v0.w=fmaxf(0.f,a*v0.w+bp);
        v1.x=fmaxf(0.f,a*v1.x+bp); v1.y=fmaxf(0.f,a*v1.y+bp);
        v1.z=fmaxf(0.f,a*v1.z+bp); v1.w=fmaxf(0.f,a*v1.w+bp);
        *(float4*)&sg[c][lane*8]   = v0;
        *(float4*)&sg[c][lane*8+4] = v1;
    }
    __syncthreads();

    int tr = wid, tc = lane;
    unsigned long long acc2[8][4];
#pragma unroll
    for (int i=0;i<8;i++)
#pragma unroll
        for (int j=0;j<4;j++) acc2[i][j]=0ull;

#pragma unroll 2
    for (int k = 0; k < 64; k++)
        MM8x8_K(&sw[k][tr*8], &sg[k][tc*8]);

    float acc[8][8];
#pragma unroll
    for (int i=0;i<8;i++)
#pragma unroll
        for (int j=0;j<4;j++) UNPACK2(acc[i][2*j], acc[i][2*j+1], acc2[i][j]);

#pragma unroll
    for (int i = 0; i < 8; i++) {
        int c = tr*8 + i;
        float* hp = d_h2 + (size_t)c*P_TOTAL + pos0 + tc*8;
        *(float4*)hp     = make_float4(acc[i][0],acc[i][1],acc[i][2],acc[i][3]);
        *(float4*)(hp+4) = make_float4(acc[i][4],acc[i][5],acc[i][6],acc[i][7]);
    }
#pragma unroll
    for (int i = 0; i < 8; i++) {
        float s = 0.f, q = 0.f;
#pragma unroll
        for (int j = 0; j < 8; j++) { s += acc[i][j]; q += acc[i][j]*acc[i][j]; }
#pragma unroll
        for (int o = 16; o > 0; o >>= 1) {
            s += __shfl_xor_sync(0xffffffffu, s, o);
            q += __shfl_xor_sync(0xffffffffu, q, o);
        }
        if (tc == 0) {
            int c = tr*8 + i;
            d_partials[((size_t)blockIdx.x*128 + c)*2 + 0] = s;
            d_partials[((size_t)blockIdx.x*128 + c)*2 + 1] = q;
        }
    }
}

// ---------------- layer 3: bn2+relu on load, GEMM(128x64), fused max/min -----
__global__ __launch_bounds__(256,2) void k_layer3(const float* __restrict__ W3) {
    extern __shared__ float sm[];
    float (*sg)[128] = (float(*)[128])sm;              // 64 x 128
    float (*sw)[128] = (float(*)[128])(sm + 64*128);   // 64 x 128
    int tid = threadIdx.x;
    int pos0 = blockIdx.x * 128;
    int wid = tid >> 5, lane = tid & 31;

    for (int i = tid; i < 128*64; i += 256) { int o = i/64, c = i%64; sw[c][o] = W3[i]; }
    for (int c = wid; c < 64; c += 8) {
        float a = d_ab[c*2], bp = d_ab[c*2+1];
        const float4* src = (const float4*)(d_h2 + (size_t)c*P_TOTAL + pos0);
        float4 v = src[lane];
        v.x=fmaxf(0.f,a*v.x+bp); v.y=fmaxf(0.f,a*v.y+bp);
        v.z=fmaxf(0.f,a*v.z+bp); v.w=fmaxf(0.f,a*v.w+bp);
        *(float4*)&sg[c][lane*4] = v;
    }
    __syncthreads();

    int tr = tid >> 4, tc = tid & 15;
    unsigned long long acc2[8][4];
#pragma unroll
    for (int i=0;i<8;i++)
#pragma unroll
        for (int j=0;j<4;j++) acc2[i][j]=0ull;

#pragma unroll 2
    for (int k = 0; k < 64; k++)
        MM8x8_K(&sw[k][tr*8], &sg[k][tc*8]);

    float acc[8][8];
#pragma unroll
    for (int i=0;i<8;i++)
#pragma unroll
        for (int j=0;j<4;j++) UNPACK2(acc[i][2*j], acc[i][2*j+1], acc2[i][j]);

    int sglob = (pos0 >> 5) + (tc >> 2);
#pragma unroll
    for (int i = 0; i < 8; i++) {
        int c = tr*8 + i;
        float mx = acc[i][0], mn = acc[i][0];
#pragma unroll
        for (int j = 1; j < 8; j++) { mx = fmaxf(mx, acc[i][j]); mn = fminf(mn, acc[i][j]); }
        mx = fmaxf(mx, __shfl_xor_sync(0xffffffffu, mx, 1));
        mn = fminf(mn, __shfl_xor_sync(0xffffffffu, mn, 1));
        mx = fmaxf(mx, __shfl_xor_sync(0xffffffffu, mx, 2));
        mn = fminf(mn, __shfl_xor_sync(0xffffffffu, mn, 2));
        if ((tc & 3) == 0) {
            d_hmx[(size_t)c*(BB*NPOINT) + sglob] = mx;
            d_hmn[(size_t)c*(BB*NPOINT) + sglob] = mn;
        }
    }
#pragma unroll
    for (int i = 0; i < 8; i++) {
        float s = 0.f, q = 0.f;
#pragma unroll
        for (int j = 0; j < 8; j++) { s += acc[i][j]; q += acc[i][j]*acc[i][j]; }
#pragma unroll
        for (int o = 8; o > 0; o >>= 1) {
            s += __shfl_xor_sync(0xffffffffu, s, o);
            q += __shfl_xor_sync(0xffffffffu, q, o);
        }
        if (tc == 0) {
            int c = tr*8 + i;
            d_partials[((size_t)blockIdx.x*128 + c)*2 + 0] = s;
            d_partials[((size_t)blockIdx.x*128 + c)*2 + 1] = q;
        }
    }
}

// ---------------- bn3 + relu on the pooled extremum --------------------------
__global__ void k_finalize(float* __restrict__ feats) {
    int gid = blockIdx.x*blockDim.x + threadIdx.x;
    if (gid >= BB*128*NPOINT) return;
    int s = gid & 2047;
    int o = (gid >> 11) & 127;
    int b = gid >> 18;
    float a = d_ab[o*2], bp = d_ab[o*2+1];
    size_t ix = (size_t)o*(BB*NPOINT) + b*NPOINT + s;
    float v = (a >= 0.0f) ? d_hmx[ix] : d_hmn[ix];
    feats[gid] = fmaxf(0.0f, a*v + bp);
}

// ---------------- launch ------------------------------------------------------
extern "C" void kernel_launch(void* const* d_in, const int* in_sizes, int n_in,
                              void* d_out, int out_size) {
    const float* xyz      = (const float*)d_in[0];
    const float* features = (const float*)d_in[1];
    const float* W1 = (const float*)d_in[2];
    const float* g1 = (const float*)d_in[3];
    const float* b1 = (const float*)d_in[4];
    const float* W2 = (const float*)d_in[5];
    const float* g2 = (const float*)d_in[6];
    const float* b2 = (const float*)d_in[7];
    const float* W3 = (const float*)d_in[8];
    const float* g3 = (const float*)d_in[9];
    const float* b3 = (const float*)d_in[10];
    float* out    = (float*)d_out;
    float* newxyz = out;                       // 8*2048*3
    float* feats  = out + BB*NPOINT*3;         // 8*128*2048

    const int SMF = 3*NN*4;                    // 96KB FPS point cache
    const int SMQ = 3*NN*4;                    // 96KB ballquery stage
    const int SM1 = (67*256 + 67*64) * 4;      // 85760
    const int SM2 = (64*256 + 64*64) * 4;      // 81920
    const int SM3 = (64*128 + 64*128) * 4;     // 65536
    cudaFuncSetAttribute(k_fps,       cudaFuncAttributeMaxDynamicSharedMemorySize, SMF);
    cudaFuncSetAttribute(k_ballquery, cudaFuncAttributeMaxDynamicSharedMemorySize, SMQ);
    cudaFuncSetAttribute(k_layer1,    cudaFuncAttributeMaxDynamicSharedMemorySize, SM1);
    cudaFuncSetAttribute(k_layer2,    cudaFuncAttributeMaxDynamicSharedMemorySize, SM2);
    cudaFuncSetAttribute(k_layer3,    cudaFuncAttributeMaxDynamicSharedMemorySize, SM3);

    k_transpose<<<dim3(NN/32, CC/32, BB), dim3(32,8)>>>(features);
    k_sort<<<BB, 1024>>>(xyz);
    k_fps<<<BB, 1024, SMF>>>(xyz, newxyz);
    k_ballquery<<<BB*64, 1024, SMQ>>>(xyz, newxyz);

    k_layer1<<<P_TOTAL/256, 256, SM1>>>(xyz, newxyz, W1);
    k_stats<<<64, 256>>>(g1, b1, P_TOTAL/256);
    k_layer2<<<P_TOTAL/256, 256, SM2>>>(W2);
    k_stats<<<64, 256>>>(g2, b2, P_TOTAL/256);
    k_layer3<<<P_TOTAL/128, 256, SM3>>>(W3);
    k_stats<<<128, 256>>>(g3, b3, P_TOTAL/128);
    k_finalize<<<(BB*128*NPOINT)/256, 256>>>(feats);
}

// round 14
// speedup vs baseline: 1.6669x; 1.0834x over previous
#include <cuda_runtime.h>
#include <stdint.h>

#define BB 8
#define NN 8192
#define CC 64
#define NPOINT 2048
#define NSAMPLE 32
#define RADIUS2 0.04f
#define P_TOTAL (BB*NPOINT*NSAMPLE)   // 524288

// ---------------- scratch (device globals; no allocation allowed) ------------
__device__ float d_featT[BB*NN*CC];                 // 16.8 MB  (B,N,C)
__device__ int   d_ball_idx[P_TOTAL];
__device__ float d_h1[(size_t)64*P_TOTAL];          // 134 MB
__device__ float d_h2[(size_t)64*P_TOTAL];          // 134 MB
__device__ float d_hmx[(size_t)128*BB*NPOINT];      // 8 MB
__device__ float d_hmn[(size_t)128*BB*NPOINT];      // 8 MB
__device__ float d_partials[4096*128*2];            // 4 MB
__device__ float d_ab[128*2];                       // fused BN scale/shift
// Morton-sorted copies of xyz (+ original index)
__device__ float d_sx[BB*NN], d_sy[BB*NN], d_sz[BB*NN];
__device__ int   d_sidx[BB*NN];

// ---------------- packed f32x2 helpers (exact per-element RN) ----------------
#define PACK2(out, lo, hi)  asm("mov.b64 %0, {%1, %2};" : "=l"(out) : "f"(lo), "f"(hi))
#define UNPACK2(lo, hi, in) asm("mov.b64 {%0, %1}, %2;" : "=f"(lo), "=f"(hi) : "l"(in))
#define ADD2(out, a, b)     asm("add.rn.f32x2 %0, %1, %2;" : "=l"(out) : "l"(a), "l"(b))
#define MUL2(out, a, b)     asm("mul.rn.f32x2 %0, %1, %2;" : "=l"(out) : "l"(a), "l"(b))
#define FMA2(d, a, b, c)    asm("fma.rn.f32x2 %0, %1, %2, %3;" : "=l"(d) : "l"(a), "l"(b), "l"(c))

// ---------------- feature transpose (B,C,N) -> (B,N,C) -----------------------
__global__ void k_transpose(const float* __restrict__ f) {
    __shared__ float tile[32][33];
    int b = blockIdx.z, n0 = blockIdx.x*32, c0 = blockIdx.y*32;
    int tx = threadIdx.x, ty = threadIdx.y;
    for (int i = ty; i < 32; i += 8)
        tile[i][tx] = f[((size_t)b*CC + c0 + i)*NN + n0 + tx];
    __syncthreads();
    for (int i = ty; i < 32; i += 8)
        d_featT[((size_t)b*NN + n0 + i)*CC + c0 + tx] = tile[tx][i];
}

// ---------------- Morton counting sort: one CTA per batch --------------------
__global__ __launch_bounds__(1024,1) void k_sort(const float* __restrict__ xyz) {
    __shared__ int cnt[4096];
    __shared__ unsigned short cell[8192];
    __shared__ int wsum[32];
    int b = blockIdx.x, t = threadIdx.x;
    for (int i = t; i < 4096; i += 1024) cnt[i] = 0;
    __syncthreads();
    const float* xb = xyz + (size_t)b*NN*3;
    for (int i = t; i < NN; i += 1024) {
        float x = xb[i*3+0], y = xb[i*3+1], z = xb[i*3+2];
        int cx = min(15, max(0, (int)(x*16.0f)));
        int cy = min(15, max(0, (int)(y*16.0f)));
        int cz = min(15, max(0, (int)(z*16.0f)));
        int m = 0;
#pragma unroll
        for (int j = 0; j < 4; j++)
            m |= (((cx>>j)&1)<<(3*j)) | (((cy>>j)&1)<<(3*j+1)) | (((cz>>j)&1)<<(3*j+2));
        cell[i] = (unsigned short)m;
        atomicAdd(&cnt[m], 1);
    }
    __syncthreads();
    int c0 = cnt[t*4+0], c1 = cnt[t*4+1], c2 = cnt[t*4+2], c3 = cnt[t*4+3];
    int ts = c0+c1+c2+c3;
    int lane = t & 31, w = t >> 5;
    int x = ts;
#pragma unroll
    for (int o = 1; o < 32; o <<= 1) {
        int y = __shfl_up_sync(0xffffffffu, x, o);
        if (lane >= o) x += y;
    }
    if (lane == 31) wsum[w] = x;
    int wex = x - ts;
    __syncthreads();
    if (w == 0) {
        int v = wsum[lane];
        int xx = v;
#pragma unroll
        for (int o = 1; o < 32; o <<= 1) {
            int y = __shfl_up_sync(0xffffffffu, xx, o);
            if (lane >= o) xx += y;
        }
        wsum[lane] = xx - v;
    }
    __syncthreads();
    int basep = wsum[w] + wex;
    cnt[t*4+0] = basep;
    cnt[t*4+1] = basep + c0;
    cnt[t*4+2] = basep + c0 + c1;
    cnt[t*4+3] = basep + c0 + c1 + c2;
    __syncthreads();
    for (int i = t; i < NN; i += 1024) {
        int m = cell[i];
        int pos = atomicAdd(&cnt[m], 1);
        d_sx[b*NN+pos] = xb[i*3+0];
        d_sy[b*NN+pos] = xb[i*3+1];
        d_sz[b*NN+pos] = xb[i*3+2];
        d_sidx[b*NN+pos] = i;
    }
}

// ---------------- FPS: 1 CTA/batch, 512 thr, 16 warps x 512 pts --------------
// Hypothesis: skip-path cost scales with warp count. One 512-pt box per warp,
// 16 pts/thread; same bit-exact dd-update, tie-break, and REDUX tail as R9.
__global__ __launch_bounds__(512,1) void k_fps(const float* __restrict__ xyz,
                                               float* __restrict__ out_newxyz) {
    extern __shared__ float smem[];
    float* s_px = smem;
    float* s_py = smem + 8192;
    float* s_pz = smem + 16384;
    __shared__ unsigned s_val[2][16];
    __shared__ unsigned s_key[2][16];

    const int b = blockIdx.x, tid = threadIdx.x;
    const int w = tid >> 5, lane = tid & 31;
    const int base = w*512 + lane*16;

    float X[16], Y[16], Z[16], dd[16];
    unsigned OIK[16];
    {
        const float* sx = d_sx + b*NN;
        const float* sy = d_sy + b*NN;
        const float* sz = d_sz + b*NN;
        const int*   si = d_sidx + b*NN;
#pragma unroll
        for (int q = 0; q < 4; q++) {
            float4 vx = *(const float4*)(sx + base + q*4);
            float4 vy = *(const float4*)(sy + base + q*4);
            float4 vz = *(const float4*)(sz + base + q*4);
            int4   vi = *(const int4*)  (si + base + q*4);
            X[q*4+0]=vx.x; X[q*4+1]=vx.y; X[q*4+2]=vx.z; X[q*4+3]=vx.w;
            Y[q*4+0]=vy.x; Y[q*4+1]=vy.y; Y[q*4+2]=vy.z; Y[q*4+3]=vy.w;
            Z[q*4+0]=vz.x; Z[q*4+1]=vz.y; Z[q*4+2]=vz.z; Z[q*4+3]=vz.w;
            OIK[q*4+0]=((unsigned)vi.x<<13)|(unsigned)(base+q*4+0);
            OIK[q*4+1]=((unsigned)vi.y<<13)|(unsigned)(base+q*4+1);
            OIK[q*4+2]=((unsigned)vi.z<<13)|(unsigned)(base+q*4+2);
            OIK[q*4+3]=((unsigned)vi.w<<13)|(unsigned)(base+q*4+3);
        }
#pragma unroll
        for (int i = 0; i < 16; i++) {
            s_px[base+i]=X[i]; s_py[base+i]=Y[i]; s_pz[base+i]=Z[i];
            dd[i]=1e10f;
        }
    }
    float bxn=X[0],bxx=X[0],byn=Y[0],byx=Y[0],bzn=Z[0],bzx=Z[0];
#pragma unroll
    for (int i = 1; i < 16; i++) {
        bxn=fminf(bxn,X[i]); bxx=fmaxf(bxx,X[i]);
        byn=fminf(byn,Y[i]); byx=fmaxf(byx,Y[i]);
        bzn=fminf(bzn,Z[i]); bzx=fmaxf(bzx,Z[i]);
    }
#pragma unroll
    for (int o = 16; o >= 1; o >>= 1) {
        bxn=fminf(bxn,__shfl_xor_sync(0xffffffffu,bxn,o));
        bxx=fmaxf(bxx,__shfl_xor_sync(0xffffffffu,bxx,o));
        byn=fminf(byn,__shfl_xor_sync(0xffffffffu,byn,o));
        byx=fmaxf(byx,__shfl_xor_sync(0xffffffffu,byx,o));
        bzn=fminf(bzn,__shfl_xor_sync(0xffffffffu,bzn,o));
        bzx=fmaxf(bzx,__shfl_xor_sync(0xffffffffu,bzx,o));
    }
    unsigned long long PX[8],PY[8],PZ[8];
#pragma unroll
    for (int j = 0; j < 8; j++) {
        PACK2(PX[j],X[2*j],X[2*j+1]);
        PACK2(PY[j],Y[2*j],Y[2*j+1]);
        PACK2(PZ[j],Z[2*j],Z[2*j+1]);
    }
    unsigned wmax = __float_as_uint(1e10f), wkey = 0xffffffffu;

    float lx, ly, lz;
    {
        const float* xb = xyz + (size_t)b*NN*3;
        lx = xb[0]; ly = xb[1]; lz = xb[2];
    }
    if (tid == 0) {
        float* o = out_newxyz + (size_t)b*NPOINT*3;
        o[0] = lx; o[1] = ly; o[2] = lz;
    }

    for (int it = 1; it < NPOINT; it++) {
        const int par = it & 1;
        float dxl = fmaxf(fmaxf(__fadd_rn(bxn,-lx), __fadd_rn(lx,-bxx)), 0.0f);
        float dyl = fmaxf(fmaxf(__fadd_rn(byn,-ly), __fadd_rn(ly,-byx)), 0.0f);
        float dzl = fmaxf(fmaxf(__fadd_rn(bzn,-lz), __fadd_rn(lz,-bzx)), 0.0f);
        float dlb = (dxl*dxl + dyl*dyl + dzl*dzl) * 0.9999f;
        if (dlb < __uint_as_float(wmax)) {
            float nlx = -lx, nly = -ly, nlz = -lz;
            unsigned long long NLX, NLY, NLZ;
            PACK2(NLX,nlx,nlx); PACK2(NLY,nly,nly); PACK2(NLZ,nlz,nlz);
            float lv = 0.0f;
#pragma unroll
            for (int j = 0; j < 8; j++) {
                unsigned long long dx,dy,dz,qx,qy,qz,t,s;
                ADD2(dx,PX[j],NLX); ADD2(dy,PY[j],NLY); ADD2(dz,PZ[j],NLZ);
                MUL2(qx,dx,dx); MUL2(qy,dy,dy); MUL2(qz,dz,dz);
                ADD2(t,qx,qy); ADD2(s,t,qz);
                float da,db; UNPACK2(da,db,s);
                dd[2*j]   = fminf(dd[2*j],da);
                dd[2*j+1] = fminf(dd[2*j+1],db);
                lv = fmaxf(lv, fmaxf(dd[2*j], dd[2*j+1]));
            }
            wmax = __reduce_max_sync(0xffffffffu, __float_as_uint(lv));
            unsigned cand = 0xffffffffu;
            if (__float_as_uint(lv) == wmax) {
#pragma unroll
                for (int i = 0; i < 16; i++)
                    if (__float_as_uint(dd[i]) == wmax) cand = min(cand, OIK[i]);
            }
            wkey = __reduce_min_sync(0xffffffffu, cand);
        }
        if (lane == 0) { s_val[par][w] = wmax; s_key[par][w] = wkey; }
        __syncthreads();
        unsigned v  = (lane < 16) ? s_val[par][lane] : 0u;
        unsigned m  = __reduce_max_sync(0xffffffffu, v);
        unsigned ck = (lane < 16 && v == m) ? s_key[par][lane] : 0xffffffffu;
        unsigned gk = __reduce_min_sync(0xffffffffu, ck);
        int p = (int)(gk & 8191u);
        lx = s_px[p]; ly = s_py[p]; lz = s_pz[p];
        if (tid == 0) {
            float* o2 = out_newxyz + ((size_t)b*NPOINT + it)*3;
            o2[0] = lx; o2[1] = ly; o2[2] = lz;
        }
    }
}

// ---------------- ball query: smem-staged, 32 queries per 1024-thr CTA -------
__global__ __launch_bounds__(1024,2) void k_ballquery(const float* __restrict__ xyz,
                                                      const float* __restrict__ newxyz) {
    extern __shared__ float sm[];
    float* sx = sm;
    float* sy = sm + 8192;
    float* sz = sm + 16384;
    int tid = threadIdx.x;
    int b = blockIdx.x >> 6;
    int qbase = (blockIdx.x & 63) * 32;

    const float* xb = xyz + (size_t)b*NN*3;
    for (int p = tid; p < NN; p += 1024) {
        sx[p] = xb[3*p+0];
        sy[p] = xb[3*p+1];
        sz[p] = xb[3*p+2];
    }
    __syncthreads();

    int w = tid >> 5, lane = tid & 31;
    int s = qbase + w;
    int gq = b*NPOINT + s;
    const float* np = newxyz + (size_t)gq*3;
    float qx = np[0], qy = np[1], qz = np[2];
    int* outp = d_ball_idx + (size_t)gq*NSAMPLE;

    int cnt = 0, firstIdx = 0; bool haveFirst = false;
    for (int j0 = 0; j0 < NN && cnt < NSAMPLE; j0 += 32) {
        int j = j0 + lane;
        float dx = __fadd_rn(sx[j], -qx);
        float dy = __fadd_rn(sy[j], -qy);
        float dz = __fadd_rn(sz[j], -qz);
        float d = __fadd_rn(__fadd_rn(__fmul_rn(dx,dx), __fmul_rn(dy,dy)),
                            __fmul_rn(dz,dz));
        bool in = d < RADIUS2;
        unsigned mm = __ballot_sync(0xffffffffu, in);
        if (mm) {
            if (!haveFirst) { firstIdx = j0 + __ffs(mm) - 1; haveFirst = true; }
            if (in) {
                int pos = cnt + __popc(mm & ((1u << lane) - 1u));
                if (pos < NSAMPLE) outp[pos] = j;
            }
            cnt += __popc(mm);
        }
    }
    int fs = cnt < NSAMPLE ? cnt : NSAMPLE;
    for (int pos = fs + lane; pos < NSAMPLE; pos += 32) outp[pos] = firstIdx;
}

// ======== packed-FMA 8x8 micro-kernel (best measured) =========================
#define MM8x8_K(sw_row, sg_row)                                               \
    do {                                                                      \
        float wv[8], g[8];                                                    \
        *(float4*)&wv[0] = *(const float4*)&(sw_row)[0];                      \
        *(float4*)&wv[4] = *(const float4*)&(sw_row)[4];                      \
        *(float4*)&g[0]  = *(const float4*)&(sg_row)[0];                      \
        *(float4*)&g[4]  = *(const float4*)&(sg_row)[4];                      \
        unsigned long long g2[4];                                             \
        PACK2(g2[0], g[0], g[1]); PACK2(g2[1], g[2], g[3]);                   \
        PACK2(g2[2], g[4], g[5]); PACK2(g2[3], g[6], g[7]);                   \
        _Pragma("unroll")                                                     \
        for (int i = 0; i < 8; i++) {                                         \
            unsigned long long w2; PACK2(w2, wv[i], wv[i]);                   \
            FMA2(acc2[i][0], w2, g2[0], acc2[i][0]);                          \
            FMA2(acc2[i][1], w2, g2[1], acc2[i][1]);                          \
            FMA2(acc2[i][2], w2, g2[2], acc2[i][2]);                          \
            FMA2(acc2[i][3], w2, g2[3], acc2[i][3]);                          \
        }                                                                     \
    } while (0)

// ---------------- layer 1: gather + GEMM(64x67) + stat partials --------------
__global__ __launch_bounds__(256,2) void k_layer1(const float* __restrict__ xyz,
                                                  const float* __restrict__ newxyz,
                                                  const float* __restrict__ W1) {
    extern __shared__ float sm[];
    float (*sg)[256] = (float(*)[256])sm;              // 67 x 256
    float (*sw)[64]  = (float(*)[64])(sm + 67*256);    // 67 x 64
    int tid = threadIdx.x;
    int pos0 = blockIdx.x * 256;

    for (int i = tid; i < 64*67; i += 256) { int o = i/67, c = i%67; sw[c][o] = W1[i]; }
    {
        int pos = pos0 + tid;
        int idx = d_ball_idx[pos];
        int b = pos >> 16;
        int s = (pos >> 5) & 2047;
        const float* nx = newxyz + ((size_t)b*NPOINT + s)*3;
        const float* pp = xyz + ((size_t)b*NN + idx)*3;
        sg[0][tid] = pp[0]-nx[0];
        sg[1][tid] = pp[1]-nx[1];
        sg[2][tid] = pp[2]-nx[2];
        const float4* fr = (const float4*)(d_featT + ((size_t)b*NN + idx)*CC);
#pragma unroll
        for (int c4 = 0; c4 < 16; c4++) {
            float4 v = fr[c4];
            sg[3+c4*4+0][tid] = v.x; sg[3+c4*4+1][tid] = v.y;
            sg[3+c4*4+2][tid] = v.z; sg[3+c4*4+3][tid] = v.w;
        }
    }
    __syncthreads();

    int tr = tid >> 5, tc = tid & 31;
    unsigned long long acc2[8][4];
#pragma unroll
    for (int i=0;i<8;i++)
#pragma unroll
        for (int j=0;j<4;j++) acc2[i][j]=0ull;

#pragma unroll 2
    for (int k = 0; k < 67; k++)
        MM8x8_K(&sw[k][tr*8], &sg[k][tc*8]);

    float acc[8][8];
#pragma unroll
    for (int i=0;i<8;i++)
#pragma unroll
        for (int j=0;j<4;j++) UNPACK2(acc[i][2*j], acc[i][2*j+1], acc2[i][j]);

#pragma unroll
    for (int i = 0; i < 8; i++) {
        int c = tr*8 + i;
        float* hp = d_h1 + (size_t)c*P_TOTAL + pos0 + tc*8;
        *(float4*)hp     = make_float4(acc[i][0],acc[i][1],acc[i][2],acc[i][3]);
        *(float4*)(hp+4) = make_float4(acc[i][4],acc[i][5],acc[i][6],acc[i][7]);
    }
#pragma unroll
    for (int i = 0; i < 8; i++) {
        float s = 0.f, q = 0.f;
#pragma unroll
        for (int j = 0; j < 8; j++) { s += acc[i][j]; q += acc[i][j]*acc[i][j]; }
#pragma unroll
        for (int o = 16; o > 0; o >>= 1) {
            s += __shfl_xor_sync(0xffffffffu, s, o);
            q += __shfl_xor_sync(0xffffffffu, q, o);
        }
        if (tc == 0) {
            int c = tr*8 + i;
            d_partials[((size_t)blockIdx.x*128 + c)*2 + 0] = s;
            d_partials[((size_t)blockIdx.x*128 + c)*2 + 1] = q;
        }
    }
}

// ---------------- deterministic stats reduce + BN fold -----------------------
__global__ void k_stats(const float* __restrict__ gam, const float* __restrict__ bet,
                        int nblocks) {
    int c = blockIdx.x, t = threadIdx.x;
    double s = 0.0, q = 0.0;
    for (int i = t; i < nblocks; i += 256) {
        s += (double)d_partials[((size_t)i*128 + c)*2 + 0];
        q += (double)d_partials[((size_t)i*128 + c)*2 + 1];
    }
    __shared__ double ss[256], qq[256];
    ss[t] = s; qq[t] = q; __syncthreads();
    for (int o = 128; o > 0; o >>= 1) {
        if (t < o) { ss[t] += ss[t+o]; qq[t] += qq[t+o]; }
        __syncthreads();
    }
    if (t == 0) {
        double mu  = ss[0] / (double)P_TOTAL;
        double var = qq[0] / (double)P_TOTAL - mu*mu;
        float a  = (float)((double)gam[c] / sqrt(var + 1e-5));
        float bp = (float)((double)bet[c] - mu * (double)a);
        d_ab[c*2] = a; d_ab[c*2+1] = bp;
    }
}

// ---------------- layer 2: bn1+relu on load, GEMM(64x64) ---------------------
__global__ __launch_bounds__(256,2) void k_layer2(const float* __restrict__ W2) {
    extern __shared__ float sm[];
    float (*sg)[256] = (float(*)[256])sm;              // 64 x 256
    float (*sw)[64]  = (float(*)[64])(sm + 64*256);    // 64 x 64
    int tid = threadIdx.x;
    int pos0 = blockIdx.x * 256;
    int wid = tid >> 5, lane = tid & 31;

    for (int i = tid; i < 64*64; i += 256) { int o = i/64, c = i%64; sw[c][o] = W2[i]; }
    for (int c = wid; c < 64; c += 8) {
        float a = d_ab[c*2], bp = d_ab[c*2+1];
        const float4* src = (const float4*)(d_h1 + (size_t)c*P_TOTAL + pos0) + lane*2;
        float4 v0 = src[0], v1 = src[1];
        v0.x=fmaxf(0.f,a*v0.x+bp); v0.y=fmaxf(0.f,a*v0.y+bp);
        v0.z=fmaxf(0.f,a*v0.z+bp); v0.w=fmaxf(0.f,a*v0.w+bp);
        v1.x=fmaxf(0.f,a*v1.x+bp); v1.y=fmaxf(0.f,a*v1.y+bp);
        v1.z=fmaxf(0.f,a*v1.z+bp); v1.w=fmaxf(0.f,a*v1.w+bp);
        *(float4*)&sg[c][lane*8]   = v0;
        *(float4*)&sg[c][lane*8+4] = v1;
    }
    __syncthreads();

    int tr = wid, tc = lane;
    unsigned long long acc2[8][4];
#pragma unroll
    for (int i=0;i<8;i++)
#pragma unroll
        for (int j=0;j<4;j++) acc2[i][j]=0ull;

#pragma unroll 2
    for (int k = 0; k < 64; k++)
        MM8x8_K(&sw[k][tr*8], &sg[k][tc*8]);

    float acc[8][8];
#pragma unroll
    for (int i=0;i<8;i++)
#pragma unroll
        for (int j=0;j<4;j++) UNPACK2(acc[i][2*j], acc[i][2*j+1], acc2[i][j]);

#pragma unroll
    for (int i = 0; i < 8; i++) {
        int c = tr*8 + i;
        float* hp = d_h2 + (size_t)c*P_TOTAL + pos0 + tc*8;
        *(float4*)hp     = make_float4(acc[i][0],acc[i][1],acc[i][2],acc[i][3]);
        *(float4*)(hp+4) = make_float4(acc[i][4],acc[i][5],acc[i][6],acc[i][7]);
    }
#pragma unroll
    for (int i = 0; i < 8; i++) {
        float s = 0.f, q = 0.f;
#pragma unroll
        for (int j = 0; j < 8; j++) { s += acc[i][j]; q += acc[i][j]*acc[i][j]; }
#pragma unroll
        for (int o = 16; o > 0; o >>= 1) {
            s += __shfl_xor_sync(0xffffffffu, s, o);
            q += __shfl_xor_sync(0xffffffffu, q, o);
        }
        if (tc == 0) {
            int c = tr*8 + i;
            d_partials[((size_t)blockIdx.x*128 + c)*2 + 0] = s;
            d_partials[((size_t)blockIdx.x*128 + c)*2 + 1] = q;
        }
    }
}

// ---------------- layer 3: bn2+relu on load, GEMM(128x64), fused max/min -----
__global__ __launch_bounds__(256,2) void k_layer3(const float* __restrict__ W3) {
    extern __shared__ float sm[];
    float (*sg)[128] = (float(*)[128])sm;              // 64 x 128
    float (*sw)[128] = (float(*)[128])(sm + 64*128);   // 64 x 128
    int tid = threadIdx.x;
    int pos0 = blockIdx.x * 128;
    int wid = tid >> 5, lane = tid & 31;

    for (int i = tid; i < 128*64; i += 256) { int o = i/64, c = i%64; sw[c][o] = W3[i]; }
    for (int c = wid; c < 64; c += 8) {
        float a = d_ab[c*2], bp = d_ab[c*2+1];
        const float4* src = (const float4*)(d_h2 + (size_t)c*P_TOTAL + pos0);
        float4 v = src[lane];
        v.x=fmaxf(0.f,a*v.x+bp); v.y=fmaxf(0.f,a*v.y+bp);
        v.z=fmaxf(0.f,a*v.z+bp); v.w=fmaxf(0.f,a*v.w+bp);
        *(float4*)&sg[c][lane*4] = v;
    }
    __syncthreads();

    int tr = tid >> 4, tc = tid & 15;
    unsigned long long acc2[8][4];
#pragma unroll
    for (int i=0;i<8;i++)
#pragma unroll
        for (int j=0;j<4;j++) acc2[i][j]=0ull;

#pragma unroll 2
    for (int k = 0; k < 64; k++)
        MM8x8_K(&sw[k][tr*8], &sg[k][tc*8]);

    float acc[8][8];
#pragma unroll
    for (int i=0;i<8;i++)
#pragma unroll
        for (int j=0;j<4;j++) UNPACK2(acc[i][2*j], acc[i][2*j+1], acc2[i][j]);

    int sglob = (pos0 >> 5) + (tc >> 2);
#pragma unroll
    for (int i = 0; i < 8; i++) {
        int c = tr*8 + i;
        float mx = acc[i][0], mn = acc[i][0];
#pragma unroll
        for (int j = 1; j < 8; j++) { mx = fmaxf(mx, acc[i][j]); mn = fminf(mn, acc[i][j]); }
        mx = fmaxf(mx, __shfl_xor_sync(0xffffffffu, mx, 1));
        mn = fminf(mn, __shfl_xor_sync(0xffffffffu, mn, 1));
        mx = fmaxf(mx, __shfl_xor_sync(0xffffffffu, mx, 2));
        mn = fminf(mn, __shfl_xor_sync(0xffffffffu, mn, 2));
        if ((tc & 3) == 0) {
            d_hmx[(size_t)c*(BB*NPOINT) + sglob] = mx;
            d_hmn[(size_t)c*(BB*NPOINT) + sglob] = mn;
        }
    }
#pragma unroll
    for (int i = 0; i < 8; i++) {
        float s = 0.f, q = 0.f;
#pragma unroll
        for (int j = 0; j < 8; j++) { s += acc[i][j]; q += acc[i][j]*acc[i][j]; }
#pragma unroll
        for (int o = 8; o > 0; o >>= 1) {
            s += __shfl_xor_sync(0xffffffffu, s, o);
            q += __shfl_xor_sync(0xffffffffu, q, o);
        }
        if (tc == 0) {
            int c = tr*8 + i;
            d_partials[((size_t)blockIdx.x*128 + c)*2 + 0] = s;
            d_partials[((size_t)blockIdx.x*128 + c)*2 + 1] = q;
        }
    }
}

// ---------------- bn3 + relu on the pooled extremum --------------------------
__global__ void k_finalize(float* __restrict__ feats) {
    int gid = blockIdx.x*blockDim.x + threadIdx.x;
    if (gid >= BB*128*NPOINT) return;
    int s = gid & 2047;
    int o = (gid >> 11) & 127;
    int b = gid >> 18;
    float a = d_ab[o*2], bp = d_ab[o*2+1];
    size_t ix = (size_t)o*(BB*NPOINT) + b*NPOINT + s;
    float v = (a >= 0.0f) ? d_hmx[ix] : d_hmn[ix];
    feats[gid] = fmaxf(0.0f, a*v + bp);
}

// ---------------- launch ------------------------------------------------------
extern "C" void kernel_launch(void* const* d_in, const int* in_sizes, int n_in,
                              void* d_out, int out_size) {
    const float* xyz      = (const float*)d_in[0];
    const float* features = (const float*)d_in[1];
    const float* W1 = (const float*)d_in[2];
    const float* g1 = (const float*)d_in[3];
    const float* b1 = (const float*)d_in[4];
    const float* W2 = (const float*)d_in[5];
    const float* g2 = (const float*)d_in[6];
    const float* b2 = (const float*)d_in[7];
    const float* W3 = (const float*)d_in[8];
    const float* g3 = (const float*)d_in[9];
    const float* b3 = (const float*)d_in[10];
    float* out    = (float*)d_out;
    float* newxyz = out;                       // 8*2048*3
    float* feats  = out + BB*NPOINT*3;         // 8*128*2048

    const int SMF = 3*NN*4;                    // 96KB FPS point cache
    const int SMQ = 3*NN*4;                    // 96KB ballquery stage
    const int SM1 = (67*256 + 67*64) * 4;      // 85760
    const int SM2 = (64*256 + 64*64) * 4;      // 81920
    const int SM3 = (64*128 + 64*128) * 4;     // 65536
    cudaFuncSetAttribute(k_fps,       cudaFuncAttributeMaxDynamicSharedMemorySize, SMF);
    cudaFuncSetAttribute(k_ballquery, cudaFuncAttributeMaxDynamicSharedMemorySize, SMQ);
    cudaFuncSetAttribute(k_layer1,    cudaFuncAttributeMaxDynamicSharedMemorySize, SM1);
    cudaFuncSetAttribute(k_layer2,    cudaFuncAttributeMaxDynamicSharedMemorySize, SM2);
    cudaFuncSetAttribute(k_layer3,    cudaFuncAttributeMaxDynamicSharedMemorySize, SM3);

    k_transpose<<<dim3(NN/32, CC/32, BB), dim3(32,8)>>>(features);
    k_sort<<<BB, 1024>>>(xyz);
    k_fps<<<BB, 512, SMF>>>(xyz, newxyz);
    k_ballquery<<<BB*64, 1024, SMQ>>>(xyz, newxyz);

    k_layer1<<<P_TOTAL/256, 256, SM1>>>(xyz, newxyz, W1);
    k_stats<<<64, 256>>>(g1, b1, P_TOTAL/256);
    k_layer2<<<P_TOTAL/256, 256, SM2>>>(W2);
    k_stats<<<64, 256>>>(g2, b2, P_TOTAL/256);
    k_layer3<<<P_TOTAL/128, 256, SM3>>>(W3);
    k_stats<<<128, 256>>>(g3, b3, P_TOTAL/128);
    k_finalize<<<(BB*128*NPOINT)/256, 256>>>(feats);
}